// round 1
// baseline (speedup 1.0000x reference)
#include <cuda_runtime.h>
#include <cuda_bf16.h>
#include <cstdint>

// Problem constants
#define Bn   2
#define Tn   2048
#define Cn   2048
#define NQn  16
#define NKVn 4
#define Hn   128
#define BTn  (Bn*Tn)        // 4096
#define SCALE 0.08838834764831845f  // 1/sqrt(128)

// ---------------- scratch (device globals; no allocation allowed) -------------
__device__ float g_qproj[BTn * NQn * Hn];      // [b*T+t][nq*H]
__device__ float g_kproj[BTn * NKVn * Hn];     // [b*T+t][nkv*H]
__device__ float g_vproj[BTn * NKVn * Hn];     // [b*T+t][nkv*H]  (used directly as V)
__device__ float g_qT[Bn * NQn * Hn * Tn];     // [b][h][d][t]
__device__ float g_kT[Bn * NKVn * Hn * Tn];    // [b][kvh][d][t]
__device__ float g_ctx[BTn * NQn * Hn];        // [b*T+t][nq*H]

// ---------------- fp32 SGEMM: C[M,N] = A[M,K] @ B[K,N] -----------------------
// 128x128 tile, TK=8, 256 threads, 8x8 microtile, double-buffered smem.
// Requires M%128==0, N%128==0, K%8==0 (holds for all our shapes).
__global__ void __launch_bounds__(256) sgemm128(const float* __restrict__ A,
                                                const float* __restrict__ B,
                                                float* __restrict__ C,
                                                int M, int N, int K) {
    __shared__ float As[2][8][128];
    __shared__ float Bs[2][8][128];
    int tid = threadIdx.x;
    int tx = tid & 15, ty = tid >> 4;
    int m0 = blockIdx.y << 7, n0 = blockIdx.x << 7;

    int arow = tid >> 1, ak = (tid & 1) << 2;     // A tile: 128 rows x 8 k
    int brow = tid >> 5, bn = (tid & 31) << 2;    // B tile: 8 k x 128 cols

    const float* Ap = A + (size_t)(m0 + arow) * K + ak;
    const float* Bp = B + (size_t)brow * N + n0 + bn;

    float4 av = *(const float4*)Ap;
    float4 bv = *(const float4*)Bp;
    As[0][ak + 0][arow] = av.x; As[0][ak + 1][arow] = av.y;
    As[0][ak + 2][arow] = av.z; As[0][ak + 3][arow] = av.w;
    *(float4*)&Bs[0][brow][bn] = bv;
    __syncthreads();

    float acc[8][8];
    #pragma unroll
    for (int i = 0; i < 8; i++)
        #pragma unroll
        for (int j = 0; j < 8; j++) acc[i][j] = 0.f;

    int nk = K >> 3;
    for (int kb = 0; kb < nk; kb++) {
        int cur = kb & 1, nxt = cur ^ 1;
        if (kb + 1 < nk) {
            av = *(const float4*)(Ap + (size_t)(kb + 1) * 8);
            bv = *(const float4*)(Bp + (size_t)(kb + 1) * 8 * N);
        }
        #pragma unroll
        for (int kk = 0; kk < 8; kk++) {
            float a[8], bb[8];
            float4 t0 = *(const float4*)&As[cur][kk][ty << 2];
            float4 t1 = *(const float4*)&As[cur][kk][64 + (ty << 2)];
            float4 t2 = *(const float4*)&Bs[cur][kk][tx << 2];
            float4 t3 = *(const float4*)&Bs[cur][kk][64 + (tx << 2)];
            a[0]=t0.x; a[1]=t0.y; a[2]=t0.z; a[3]=t0.w;
            a[4]=t1.x; a[5]=t1.y; a[6]=t1.z; a[7]=t1.w;
            bb[0]=t2.x; bb[1]=t2.y; bb[2]=t2.z; bb[3]=t2.w;
            bb[4]=t3.x; bb[5]=t3.y; bb[6]=t3.z; bb[7]=t3.w;
            #pragma unroll
            for (int i = 0; i < 8; i++)
                #pragma unroll
                for (int j = 0; j < 8; j++)
                    acc[i][j] += a[i] * bb[j];
        }
        if (kb + 1 < nk) {
            As[nxt][ak + 0][arow] = av.x; As[nxt][ak + 1][arow] = av.y;
            As[nxt][ak + 2][arow] = av.z; As[nxt][ak + 3][arow] = av.w;
            *(float4*)&Bs[nxt][brow][bn] = bv;
        }
        __syncthreads();
    }

    #pragma unroll
    for (int i = 0; i < 8; i++) {
        int row = m0 + ((i < 4) ? ((ty << 2) + i) : (64 + (ty << 2) + i - 4));
        float4 w0 = make_float4(acc[i][0], acc[i][1], acc[i][2], acc[i][3]);
        float4 w1 = make_float4(acc[i][4], acc[i][5], acc[i][6], acc[i][7]);
        *(float4*)&C[(size_t)row * N + n0 + (tx << 2)] = w0;
        *(float4*)&C[(size_t)row * N + n0 + 64 + (tx << 2)] = w1;
    }
}

// ---------------- RMSNorm + RoPE, writes d-major transposed ------------------
// One warp per (b,t,head) row of H=128.  out[((b*NH+h)*H + d)*T + t]
__global__ void normrope_kernel(const float* __restrict__ proj,
                                const float* __restrict__ w,
                                const float* __restrict__ cosb,
                                const float* __restrict__ sinb,
                                float* __restrict__ outT, int NH) {
    int gw = (blockIdx.x * blockDim.x + threadIdx.x) >> 5;
    int lane = threadIdx.x & 31;
    if (gw >= Bn * Tn * NH) return;
    int h = gw % NH;
    int bt = gw / NH;            // b*T + t
    int t = bt % Tn;
    int b = bt / Tn;

    const float* p = proj + (size_t)gw * Hn;
    float x0 = p[lane], x1 = p[lane + 32], x2 = p[lane + 64], x3 = p[lane + 96];
    float ss = x0 * x0 + x1 * x1 + x2 * x2 + x3 * x3;
    #pragma unroll
    for (int o = 16; o; o >>= 1) ss += __shfl_xor_sync(0xffffffffu, ss, o);
    float inv = rsqrtf(ss * (1.0f / 128.0f) + 1e-6f);
    x0 = x0 * inv * w[lane];
    x1 = x1 * inv * w[lane + 32];
    x2 = x2 * inv * w[lane + 64];
    x3 = x3 * inv * w[lane + 96];
    const float* cp = cosb + (size_t)t * Hn;
    const float* sp = sinb + (size_t)t * Hn;
    // rotate_half: d<64 -> -x[d+64] ; d>=64 -> x[d-64]
    float y0 = x0 * cp[lane]      - x2 * sp[lane];
    float y1 = x1 * cp[lane + 32] - x3 * sp[lane + 32];
    float y2 = x2 * cp[lane + 64] + x0 * sp[lane + 64];
    float y3 = x3 * cp[lane + 96] + x1 * sp[lane + 96];
    float* o = outT + ((size_t)(b * NH + h) * Hn) * Tn + t;
    o[(size_t)lane * Tn]        = y0;
    o[(size_t)(lane + 32) * Tn] = y1;
    o[(size_t)(lane + 64) * Tn] = y2;
    o[(size_t)(lane + 96) * Tn] = y3;
}

// ---------------- Flash attention (fp32, causal, GQA) ------------------------
// Grid: (T/64, NQ, B); 256 threads (16x16); per-thread 4x4 score frag,
// O frag = 4 rows x 8 cols (two float4-split column groups).
#define ATT_SMEM_BYTES ((128*64 + 128*64 + 64*128 + 64*68) * 4)
__global__ void __launch_bounds__(256) attn_kernel(const float* __restrict__ qT,
                                                   const float* __restrict__ kT,
                                                   const float* __restrict__ vproj,
                                                   float* __restrict__ ctx) {
    extern __shared__ float sm[];
    float* Qt = sm;                 // [128][64]  d-major
    float* Kt = Qt + 128 * 64;      // [128][64]  d-major
    float* Vs = Kt + 128 * 64;      // [64][128]  row-major
    float* Ps = Vs + 64 * 128;      // [64][68]   padded

    int tid = threadIdx.x;
    int tx = tid & 15, ty = tid >> 4;
    int q0 = blockIdx.x << 6;
    int h = blockIdx.y, b = blockIdx.z;
    int kvh = h >> 2;               // NQ/NKV = 4

    const float* qb = qT + (size_t)(b * NQn + h) * Hn * Tn;
    const float* kb = kT + (size_t)(b * NKVn + kvh) * Hn * Tn;
    const float* vb = vproj + (size_t)b * Tn * (NKVn * Hn) + kvh * Hn;

    // Load Q tile (once): Qt[d][r] from qb[d*T + q0 + r]
    #pragma unroll
    for (int it = 0; it < 8; it++) {
        int idx = tid + it * 256;
        int d = idx >> 4, r4 = (idx & 15) << 2;
        *(float4*)&Qt[d * 64 + r4] = *(const float4*)(qb + (size_t)d * Tn + q0 + r4);
    }

    float m_i[4], l_i[4], o_acc[4][8];
    #pragma unroll
    for (int i = 0; i < 4; i++) {
        m_i[i] = -1e30f; l_i[i] = 0.f;
        #pragma unroll
        for (int c = 0; c < 8; c++) o_acc[i][c] = 0.f;
    }
    __syncthreads();

    for (int j0 = 0; j0 <= q0; j0 += 64) {
        __syncthreads();  // protect Kt/Vs/Ps from previous iteration readers
        #pragma unroll
        for (int it = 0; it < 8; it++) {
            int idx = tid + it * 256;
            int d = idx >> 4, r4 = (idx & 15) << 2;
            *(float4*)&Kt[d * 64 + r4] = *(const float4*)(kb + (size_t)d * Tn + j0 + r4);
        }
        #pragma unroll
        for (int it = 0; it < 8; it++) {
            int idx = tid + it * 256;
            int r = idx >> 5, c4 = (idx & 31) << 2;
            *(float4*)&Vs[r * 128 + c4] =
                *(const float4*)(vb + (size_t)(j0 + r) * (NKVn * Hn) + c4);
        }
        __syncthreads();

        // S = Q @ K^T  (4x4 fragment per thread)
        float s[4][4];
        #pragma unroll
        for (int i = 0; i < 4; i++)
            #pragma unroll
            for (int j = 0; j < 4; j++) s[i][j] = 0.f;
        #pragma unroll 4
        for (int d = 0; d < 128; d++) {
            float4 a = *(const float4*)&Qt[d * 64 + (ty << 2)];
            float4 k4 = *(const float4*)&Kt[d * 64 + (tx << 2)];
            float ar[4] = {a.x, a.y, a.z, a.w};
            float kr[4] = {k4.x, k4.y, k4.z, k4.w};
            #pragma unroll
            for (int i = 0; i < 4; i++)
                #pragma unroll
                for (int j = 0; j < 4; j++)
                    s[i][j] += ar[i] * kr[j];
        }

        bool diag = (j0 == q0);
        #pragma unroll
        for (int i = 0; i < 4; i++)
            #pragma unroll
            for (int j = 0; j < 4; j++) {
                float v = s[i][j] * SCALE;
                if (diag && ((tx << 2) + j) > ((ty << 2) + i)) v = -1e30f;
                s[i][j] = v;
            }

        // online softmax per row
        #pragma unroll
        for (int i = 0; i < 4; i++) {
            float mt = fmaxf(fmaxf(s[i][0], s[i][1]), fmaxf(s[i][2], s[i][3]));
            #pragma unroll
            for (int o = 8; o; o >>= 1) mt = fmaxf(mt, __shfl_xor_sync(0xffffffffu, mt, o));
            float mn = fmaxf(m_i[i], mt);
            float al = __expf(m_i[i] - mn);
            m_i[i] = mn;
            float rs = 0.f;
            #pragma unroll
            for (int j = 0; j < 4; j++) { s[i][j] = __expf(s[i][j] - mn); rs += s[i][j]; }
            #pragma unroll
            for (int o = 8; o; o >>= 1) rs += __shfl_xor_sync(0xffffffffu, rs, o);
            l_i[i] = l_i[i] * al + rs;
            #pragma unroll
            for (int c = 0; c < 8; c++) o_acc[i][c] *= al;
            *(float4*)&Ps[((ty << 2) + i) * 68 + (tx << 2)] =
                make_float4(s[i][0], s[i][1], s[i][2], s[i][3]);
        }
        __syncthreads();

        // O += P @ V
        #pragma unroll 4
        for (int jj = 0; jj < 64; jj++) {
            float4 v0 = *(const float4*)&Vs[jj * 128 + (tx << 2)];
            float4 v1 = *(const float4*)&Vs[jj * 128 + 64 + (tx << 2)];
            #pragma unroll
            for (int i = 0; i < 4; i++) {
                float pp = Ps[((ty << 2) + i) * 68 + jj];
                o_acc[i][0] += pp * v0.x; o_acc[i][1] += pp * v0.y;
                o_acc[i][2] += pp * v0.z; o_acc[i][3] += pp * v0.w;
                o_acc[i][4] += pp * v1.x; o_acc[i][5] += pp * v1.y;
                o_acc[i][6] += pp * v1.z; o_acc[i][7] += pp * v1.w;
            }
        }
    }

    // epilogue: normalize, write ctx[b*T+row][h*128 + col]
    #pragma unroll
    for (int i = 0; i < 4; i++) {
        int row = q0 + (ty << 2) + i;
        float inv = 1.0f / l_i[i];
        float4 w0 = make_float4(o_acc[i][0]*inv, o_acc[i][1]*inv, o_acc[i][2]*inv, o_acc[i][3]*inv);
        float4 w1 = make_float4(o_acc[i][4]*inv, o_acc[i][5]*inv, o_acc[i][6]*inv, o_acc[i][7]*inv);
        float* outp = ctx + (size_t)(b * Tn + row) * (NQn * Hn) + h * Hn;
        *(float4*)&outp[(tx << 2)] = w0;
        *(float4*)&outp[64 + (tx << 2)] = w1;
    }
}

// ---------------- launch ------------------------------------------------------
extern "C" void kernel_launch(void* const* d_in, const int* in_sizes, int n_in,
                              void* d_out, int out_size) {
    (void)in_sizes; (void)n_in; (void)out_size;
    const float* x   = (const float*)d_in[0];
    const float* Wq  = (const float*)d_in[1];
    const float* Wk  = (const float*)d_in[2];
    const float* Wv  = (const float*)d_in[3];
    const float* Wo  = (const float*)d_in[4];
    const float* qnw = (const float*)d_in[5];
    const float* knw = (const float*)d_in[6];
    const float* cosb = (const float*)d_in[7];
    const float* sinb = (const float*)d_in[8];
    // d_in[9] = attn_mask (pure causal; handled analytically)
    float* out = (float*)d_out;

    float *qp, *kp, *vp, *qT, *kT, *ctx;
    cudaGetSymbolAddress((void**)&qp,  g_qproj);
    cudaGetSymbolAddress((void**)&kp,  g_kproj);
    cudaGetSymbolAddress((void**)&vp,  g_vproj);
    cudaGetSymbolAddress((void**)&qT,  g_qT);
    cudaGetSymbolAddress((void**)&kT,  g_kT);
    cudaGetSymbolAddress((void**)&ctx, g_ctx);

    cudaFuncSetAttribute(attn_kernel, cudaFuncAttributeMaxDynamicSharedMemorySize,
                         ATT_SMEM_BYTES);

    // 1) projections
    sgemm128<<<dim3(Cn / 128, BTn / 128), 256>>>(x, Wq, qp, BTn, NQn * Hn, Cn);
    sgemm128<<<dim3((NKVn * Hn) / 128, BTn / 128), 256>>>(x, Wk, kp, BTn, NKVn * Hn, Cn);
    sgemm128<<<dim3((NKVn * Hn) / 128, BTn / 128), 256>>>(x, Wv, vp, BTn, NKVn * Hn, Cn);

    // 2) rmsnorm + rope (q, k) -> d-major transposed buffers
    {
        int warps_q = Bn * Tn * NQn;            // 65536
        normrope_kernel<<<warps_q / 8, 256>>>(qp, qnw, cosb, sinb, qT, NQn);
        int warps_k = Bn * Tn * NKVn;           // 16384
        normrope_kernel<<<warps_k / 8, 256>>>(kp, knw, cosb, sinb, kT, NKVn);
    }

    // 3) causal GQA flash attention
    attn_kernel<<<dim3(Tn / 64, NQn, Bn), 256, ATT_SMEM_BYTES>>>(qT, kT, vp, ctx);

    // 4) output projection
    sgemm128<<<dim3(Cn / 128, BTn / 128), 256>>>(ctx, Wo, out, BTn, Cn, Cn);
}

// round 3
// speedup vs baseline: 1.9251x; 1.9251x over previous
#include <cuda_runtime.h>
#include <cuda_fp16.h>
#include <cstdint>

// Problem constants
#define Bn   2
#define Tn   2048
#define Cn   2048
#define NQn  16
#define NKVn 4
#define Hn   128
#define BTn  (Bn*Tn)        // 4096
#define SCALE 0.08838834764831845f  // 1/sqrt(128)

// ---------------- scratch (device globals) ------------------------------------
__device__ float  g_qproj[BTn * NQn * Hn];
__device__ float  g_kproj[BTn * NKVn * Hn];
__device__ float  g_vproj[BTn * NKVn * Hn];
__device__ float  g_qT[Bn * NQn * Hn * Tn];      // [b][h][d][t]
__device__ float  g_kT[Bn * NKVn * Hn * Tn];     // [b][kvh][d][t]
__device__ __half g_xh[BTn * Cn];                // x fp16 [M][K]
__device__ __half g_wqh[(NQn*Hn) * Cn];          // W^T fp16 [N][K]
__device__ __half g_wkh[(NKVn*Hn) * Cn];
__device__ __half g_wvh[(NKVn*Hn) * Cn];
__device__ __half g_woh[Cn * (NQn*Hn)];
__device__ __half g_ctxh[BTn * NQn * Hn];        // attention out fp16 [M][K]

// ---------------- helpers ------------------------------------------------------
__device__ __forceinline__ uint32_t smem_u32(const void* p) {
    uint32_t a;
    asm("{ .reg .u64 t; cvta.to.shared.u64 t, %1; cvt.u32.u64 %0, t; }" : "=r"(a) : "l"(p));
    return a;
}
__device__ __forceinline__ void ldmatrix_x4(uint32_t& r0, uint32_t& r1,
                                            uint32_t& r2, uint32_t& r3, uint32_t addr) {
    asm volatile("ldmatrix.sync.aligned.m8n8.x4.shared.b16 {%0,%1,%2,%3}, [%4];"
                 : "=r"(r0), "=r"(r1), "=r"(r2), "=r"(r3) : "r"(addr));
}
__device__ __forceinline__ void mma16816(float* d, const uint32_t* a, const uint32_t* b) {
    asm volatile(
        "mma.sync.aligned.m16n8k16.row.col.f32.f16.f16.f32 "
        "{%0,%1,%2,%3}, {%4,%5,%6,%7}, {%8,%9}, {%0,%1,%2,%3};"
        : "+f"(d[0]), "+f"(d[1]), "+f"(d[2]), "+f"(d[3])
        : "r"(a[0]), "r"(a[1]), "r"(a[2]), "r"(a[3]), "r"(b[0]), "r"(b[1]));
}

// ---------------- fp32 -> fp16 elementwise ------------------------------------
__global__ void f32_to_f16_kernel(const float* __restrict__ in, __half* __restrict__ out, int n4) {
    int i = blockIdx.x * blockDim.x + threadIdx.x;
    if (i < n4) {
        float4 v = ((const float4*)in)[i];
        ((__half2*)out)[2*i]   = __floats2half2_rn(v.x, v.y);
        ((__half2*)out)[2*i+1] = __floats2half2_rn(v.z, v.w);
    }
}

// ---------------- W [K][N] f32 -> Wt [N][K] f16 (tiled transpose) --------------
__global__ void transpose_to_f16_kernel(const float* __restrict__ W, __half* __restrict__ Wt,
                                        int K, int N) {
    __shared__ float tile[32][33];
    int n0 = blockIdx.x * 32, k0 = blockIdx.y * 32;
    int tx = threadIdx.x, ty = threadIdx.y;   // 32 x 8
    #pragma unroll
    for (int i = 0; i < 32; i += 8)
        tile[ty + i][tx] = W[(size_t)(k0 + ty + i) * N + n0 + tx];
    __syncthreads();
    #pragma unroll
    for (int i = 0; i < 32; i += 8)
        Wt[(size_t)(n0 + ty + i) * K + k0 + tx] = __float2half(tile[tx][ty + i]);
}

// ---------------- HMMA fp16 GEMM: C[M,N]f32 = A[M,K]f16 @ Bt[N,K]f16^T ---------
// CTA 128x128, K-chunk 32, 8 warps (2m x 4n), warp tile 64x32.
// smem rows padded to 40 halfs (80B): ldmatrix stride 5*16B mod 8 -> conflict-free.
#define GP 40
__global__ void __launch_bounds__(256) hgemm_mma(const __half* __restrict__ A,
                                                 const __half* __restrict__ B,
                                                 float* __restrict__ C,
                                                 int M, int N, int K) {
    __shared__ __half As[2][128][GP];
    __shared__ __half Bs[2][128][GP];
    int tid = threadIdx.x;
    int lane = tid & 31, wid = tid >> 5;
    int wm = wid >> 2, wn = wid & 3;        // 2 x 4 warp grid
    int m0 = blockIdx.y << 7, n0 = blockIdx.x << 7;

    // g2s mapping: flat -> row (128), chunk (4 x 8 halfs)
    int r0 = tid >> 2, c0 = (tid & 3) * 8;
    int r1 = r0 + 64;
    const __half* Ap0 = A + (size_t)(m0 + r0) * K + c0;
    const __half* Ap1 = A + (size_t)(m0 + r1) * K + c0;
    const __half* Bp0 = B + (size_t)(n0 + r0) * K + c0;
    const __half* Bp1 = B + (size_t)(n0 + r1) * K + c0;

    // load chunk 0
    *(uint4*)&As[0][r0][c0] = *(const uint4*)Ap0;
    *(uint4*)&As[0][r1][c0] = *(const uint4*)Ap1;
    *(uint4*)&Bs[0][r0][c0] = *(const uint4*)Bp0;
    *(uint4*)&Bs[0][r1][c0] = *(const uint4*)Bp1;

    float acc[4][4][4];
    #pragma unroll
    for (int i = 0; i < 4; i++)
        #pragma unroll
        for (int j = 0; j < 4; j++)
            #pragma unroll
            for (int k = 0; k < 4; k++) acc[i][j][k] = 0.f;

    __syncthreads();

    int lrow = lane & 15, lhalf = lane >> 4;
    const int NC = K >> 5;
    uint4 pa0, pa1, pb0, pb1;

    for (int c = 0; c < NC; c++) {
        int cur = c & 1;
        if (c + 1 < NC) {
            pa0 = *(const uint4*)(Ap0 + (c + 1) * 32);
            pa1 = *(const uint4*)(Ap1 + (c + 1) * 32);
            pb0 = *(const uint4*)(Bp0 + (c + 1) * 32);
            pb1 = *(const uint4*)(Bp1 + (c + 1) * 32);
        }

        // load fragments
        uint32_t af[4][2][4];   // [mt][ks][4]
        uint32_t bf[4][2][2];   // [nt][ks][2]
        #pragma unroll
        for (int mt = 0; mt < 4; mt++) {
            #pragma unroll
            for (int ks = 0; ks < 2; ks++) {
                uint32_t ad = smem_u32(&As[cur][wm*64 + mt*16 + lrow][ks*16 + lhalf*8]);
                ldmatrix_x4(af[mt][ks][0], af[mt][ks][1], af[mt][ks][2], af[mt][ks][3], ad);
            }
        }
        #pragma unroll
        for (int np = 0; np < 2; np++) {
            #pragma unroll
            for (int ks = 0; ks < 2; ks++) {
                uint32_t bd = smem_u32(&Bs[cur][wn*32 + np*16 + lrow][ks*16 + lhalf*8]);
                uint32_t q0, q1, q2, q3;
                ldmatrix_x4(q0, q1, q2, q3, bd);
                bf[np*2+0][ks][0] = q0; bf[np*2+1][ks][0] = q1;
                bf[np*2+0][ks][1] = q2; bf[np*2+1][ks][1] = q3;
            }
        }
        #pragma unroll
        for (int mt = 0; mt < 4; mt++)
            #pragma unroll
            for (int nt = 0; nt < 4; nt++) {
                mma16816(acc[mt][nt], af[mt][0], bf[nt][0]);
                mma16816(acc[mt][nt], af[mt][1], bf[nt][1]);
            }

        if (c + 1 < NC) {
            int nxt = cur ^ 1;
            *(uint4*)&As[nxt][r0][c0] = pa0;
            *(uint4*)&As[nxt][r1][c0] = pa1;
            *(uint4*)&Bs[nxt][r0][c0] = pb0;
            *(uint4*)&Bs[nxt][r1][c0] = pb1;
        }
        __syncthreads();
    }

    // epilogue: row = m0 + wm*64 + mt*16 + lane/4 (+8), col = n0 + wn*32 + nt*8 + 2*(lane%4)
    int er = lane >> 2, ec = (lane & 3) * 2;
    #pragma unroll
    for (int mt = 0; mt < 4; mt++) {
        int row = m0 + wm*64 + mt*16 + er;
        float* Cr0 = C + (size_t)row * N + n0 + wn*32;
        float* Cr1 = Cr0 + 8 * N;
        #pragma unroll
        for (int nt = 0; nt < 4; nt++) {
            *(float2*)&Cr0[nt*8 + ec] = make_float2(acc[mt][nt][0], acc[mt][nt][1]);
            *(float2*)&Cr1[nt*8 + ec] = make_float2(acc[mt][nt][2], acc[mt][nt][3]);
        }
    }
}

// ---------------- RMSNorm + RoPE, writes d-major transposed ------------------
__global__ void normrope_kernel(const float* __restrict__ proj,
                                const float* __restrict__ w,
                                const float* __restrict__ cosb,
                                const float* __restrict__ sinb,
                                float* __restrict__ outT, int NH) {
    int gw = (blockIdx.x * blockDim.x + threadIdx.x) >> 5;
    int lane = threadIdx.x & 31;
    if (gw >= Bn * Tn * NH) return;
    int h = gw % NH;
    int bt = gw / NH;
    int t = bt % Tn;
    int b = bt / Tn;

    const float* p = proj + (size_t)gw * Hn;
    float x0 = p[lane], x1 = p[lane + 32], x2 = p[lane + 64], x3 = p[lane + 96];
    float ss = x0 * x0 + x1 * x1 + x2 * x2 + x3 * x3;
    #pragma unroll
    for (int o = 16; o; o >>= 1) ss += __shfl_xor_sync(0xffffffffu, ss, o);
    float inv = rsqrtf(ss * (1.0f / 128.0f) + 1e-6f);
    x0 = x0 * inv * w[lane];
    x1 = x1 * inv * w[lane + 32];
    x2 = x2 * inv * w[lane + 64];
    x3 = x3 * inv * w[lane + 96];
    const float* cp = cosb + (size_t)t * Hn;
    const float* sp = sinb + (size_t)t * Hn;
    float y0 = x0 * cp[lane]      - x2 * sp[lane];
    float y1 = x1 * cp[lane + 32] - x3 * sp[lane + 32];
    float y2 = x2 * cp[lane + 64] + x0 * sp[lane + 64];
    float y3 = x3 * cp[lane + 96] + x1 * sp[lane + 96];
    float* o = outT + ((size_t)(b * NH + h) * Hn) * Tn + t;
    o[(size_t)lane * Tn]        = y0;
    o[(size_t)(lane + 32) * Tn] = y1;
    o[(size_t)(lane + 64) * Tn] = y2;
    o[(size_t)(lane + 96) * Tn] = y3;
}

// ---------------- Flash attention (fp32, causal, GQA) ------------------------
#define ATT_SMEM_BYTES ((128*64 + 128*64 + 64*128 + 64*68) * 4)
__global__ void __launch_bounds__(256) attn_kernel(const float* __restrict__ qT,
                                                   const float* __restrict__ kT,
                                                   const float* __restrict__ vproj,
                                                   __half* __restrict__ ctxh) {
    extern __shared__ float sm[];
    float* Qt = sm;                 // [128][64]  d-major
    float* Kt = Qt + 128 * 64;      // [128][64]  d-major
    float* Vs = Kt + 128 * 64;      // [64][128]  row-major
    float* Ps = Vs + 64 * 128;      // [64][68]   padded

    int tid = threadIdx.x;
    int tx = tid & 15, ty = tid >> 4;
    int q0 = blockIdx.x << 6;
    int h = blockIdx.y, b = blockIdx.z;
    int kvh = h >> 2;

    const float* qb = qT + (size_t)(b * NQn + h) * Hn * Tn;
    const float* kb = kT + (size_t)(b * NKVn + kvh) * Hn * Tn;
    const float* vb = vproj + (size_t)b * Tn * (NKVn * Hn) + kvh * Hn;

    #pragma unroll
    for (int it = 0; it < 8; it++) {
        int idx = tid + it * 256;
        int d = idx >> 4, r4 = (idx & 15) << 2;
        *(float4*)&Qt[d * 64 + r4] = *(const float4*)(qb + (size_t)d * Tn + q0 + r4);
    }

    float m_i[4], l_i[4], o_acc[4][8];
    #pragma unroll
    for (int i = 0; i < 4; i++) {
        m_i[i] = -1e30f; l_i[i] = 0.f;
        #pragma unroll
        for (int c = 0; c < 8; c++) o_acc[i][c] = 0.f;
    }
    __syncthreads();

    for (int j0 = 0; j0 <= q0; j0 += 64) {
        __syncthreads();
        #pragma unroll
        for (int it = 0; it < 8; it++) {
            int idx = tid + it * 256;
            int d = idx >> 4, r4 = (idx & 15) << 2;
            *(float4*)&Kt[d * 64 + r4] = *(const float4*)(kb + (size_t)d * Tn + j0 + r4);
        }
        #pragma unroll
        for (int it = 0; it < 8; it++) {
            int idx = tid + it * 256;
            int r = idx >> 5, c4 = (idx & 31) << 2;
            *(float4*)&Vs[r * 128 + c4] =
                *(const float4*)(vb + (size_t)(j0 + r) * (NKVn * Hn) + c4);
        }
        __syncthreads();

        float s[4][4];
        #pragma unroll
        for (int i = 0; i < 4; i++)
            #pragma unroll
            for (int j = 0; j < 4; j++) s[i][j] = 0.f;
        #pragma unroll 4
        for (int d = 0; d < 128; d++) {
            float4 a = *(const float4*)&Qt[d * 64 + (ty << 2)];
            float4 k4 = *(const float4*)&Kt[d * 64 + (tx << 2)];
            float ar[4] = {a.x, a.y, a.z, a.w};
            float kr[4] = {k4.x, k4.y, k4.z, k4.w};
            #pragma unroll
            for (int i = 0; i < 4; i++)
                #pragma unroll
                for (int j = 0; j < 4; j++)
                    s[i][j] += ar[i] * kr[j];
        }

        bool diag = (j0 == q0);
        #pragma unroll
        for (int i = 0; i < 4; i++)
            #pragma unroll
            for (int j = 0; j < 4; j++) {
                float v = s[i][j] * SCALE;
                if (diag && ((tx << 2) + j) > ((ty << 2) + i)) v = -1e30f;
                s[i][j] = v;
            }

        #pragma unroll
        for (int i = 0; i < 4; i++) {
            float mt = fmaxf(fmaxf(s[i][0], s[i][1]), fmaxf(s[i][2], s[i][3]));
            #pragma unroll
            for (int o = 8; o; o >>= 1) mt = fmaxf(mt, __shfl_xor_sync(0xffffffffu, mt, o));
            float mn = fmaxf(m_i[i], mt);
            float al = __expf(m_i[i] - mn);
            m_i[i] = mn;
            float rs = 0.f;
            #pragma unroll
            for (int j = 0; j < 4; j++) { s[i][j] = __expf(s[i][j] - mn); rs += s[i][j]; }
            #pragma unroll
            for (int o = 8; o; o >>= 1) rs += __shfl_xor_sync(0xffffffffu, rs, o);
            l_i[i] = l_i[i] * al + rs;
            #pragma unroll
            for (int c = 0; c < 8; c++) o_acc[i][c] *= al;
            *(float4*)&Ps[((ty << 2) + i) * 68 + (tx << 2)] =
                make_float4(s[i][0], s[i][1], s[i][2], s[i][3]);
        }
        __syncthreads();

        #pragma unroll 4
        for (int jj = 0; jj < 64; jj++) {
            float4 v0 = *(const float4*)&Vs[jj * 128 + (tx << 2)];
            float4 v1 = *(const float4*)&Vs[jj * 128 + 64 + (tx << 2)];
            #pragma unroll
            for (int i = 0; i < 4; i++) {
                float pp = Ps[((ty << 2) + i) * 68 + jj];
                o_acc[i][0] += pp * v0.x; o_acc[i][1] += pp * v0.y;
                o_acc[i][2] += pp * v0.z; o_acc[i][3] += pp * v0.w;
                o_acc[i][4] += pp * v1.x; o_acc[i][5] += pp * v1.y;
                o_acc[i][6] += pp * v1.z; o_acc[i][7] += pp * v1.w;
            }
        }
    }

    #pragma unroll
    for (int i = 0; i < 4; i++) {
        int row = q0 + (ty << 2) + i;
        float inv = 1.0f / l_i[i];
        __half* outp = ctxh + (size_t)(b * Tn + row) * (NQn * Hn) + h * Hn;
        *(__half2*)&outp[(tx << 2)]     = __floats2half2_rn(o_acc[i][0]*inv, o_acc[i][1]*inv);
        *(__half2*)&outp[(tx << 2) + 2] = __floats2half2_rn(o_acc[i][2]*inv, o_acc[i][3]*inv);
        *(__half2*)&outp[64 + (tx << 2)]     = __floats2half2_rn(o_acc[i][4]*inv, o_acc[i][5]*inv);
        *(__half2*)&outp[64 + (tx << 2) + 2] = __floats2half2_rn(o_acc[i][6]*inv, o_acc[i][7]*inv);
    }
}

// ---------------- launch ------------------------------------------------------
extern "C" void kernel_launch(void* const* d_in, const int* in_sizes, int n_in,
                              void* d_out, int out_size) {
    (void)in_sizes; (void)n_in; (void)out_size;
    const float* x   = (const float*)d_in[0];
    const float* Wq  = (const float*)d_in[1];
    const float* Wk  = (const float*)d_in[2];
    const float* Wv  = (const float*)d_in[3];
    const float* Wo  = (const float*)d_in[4];
    const float* qnw = (const float*)d_in[5];
    const float* knw = (const float*)d_in[6];
    const float* cosb = (const float*)d_in[7];
    const float* sinb = (const float*)d_in[8];
    float* out = (float*)d_out;

    float *qp, *kp, *vp, *qT, *kT;
    __half *xh, *wqh, *wkh, *wvh, *woh, *ctxh;
    cudaGetSymbolAddress((void**)&qp,  g_qproj);
    cudaGetSymbolAddress((void**)&kp,  g_kproj);
    cudaGetSymbolAddress((void**)&vp,  g_vproj);
    cudaGetSymbolAddress((void**)&qT,  g_qT);
    cudaGetSymbolAddress((void**)&kT,  g_kT);
    cudaGetSymbolAddress((void**)&xh,  g_xh);
    cudaGetSymbolAddress((void**)&wqh, g_wqh);
    cudaGetSymbolAddress((void**)&wkh, g_wkh);
    cudaGetSymbolAddress((void**)&wvh, g_wvh);
    cudaGetSymbolAddress((void**)&woh, g_woh);
    cudaGetSymbolAddress((void**)&ctxh, g_ctxh);

    cudaFuncSetAttribute(attn_kernel, cudaFuncAttributeMaxDynamicSharedMemorySize,
                         ATT_SMEM_BYTES);

    // 0) conversions
    f32_to_f16_kernel<<<(BTn * Cn / 4 + 255) / 256, 256>>>(x, xh, BTn * Cn / 4);
    transpose_to_f16_kernel<<<dim3((NQn*Hn)/32, Cn/32), dim3(32, 8)>>>(Wq, wqh, Cn, NQn*Hn);
    transpose_to_f16_kernel<<<dim3((NKVn*Hn)/32, Cn/32), dim3(32, 8)>>>(Wk, wkh, Cn, NKVn*Hn);
    transpose_to_f16_kernel<<<dim3((NKVn*Hn)/32, Cn/32), dim3(32, 8)>>>(Wv, wvh, Cn, NKVn*Hn);
    transpose_to_f16_kernel<<<dim3(Cn/32, (NQn*Hn)/32), dim3(32, 8)>>>(Wo, woh, NQn*Hn, Cn);

    // 1) projections (HMMA fp16)
    hgemm_mma<<<dim3((NQn*Hn)/128, BTn/128), 256>>>(xh, wqh, qp, BTn, NQn*Hn, Cn);
    hgemm_mma<<<dim3((NKVn*Hn)/128, BTn/128), 256>>>(xh, wkh, kp, BTn, NKVn*Hn, Cn);
    hgemm_mma<<<dim3((NKVn*Hn)/128, BTn/128), 256>>>(xh, wvh, vp, BTn, NKVn*Hn, Cn);

    // 2) rmsnorm + rope -> d-major transposed
    normrope_kernel<<<(Bn * Tn * NQn) / 8, 256>>>(qp, qnw, cosb, sinb, qT, NQn);
    normrope_kernel<<<(Bn * Tn * NKVn) / 8, 256>>>(kp, knw, cosb, sinb, kT, NKVn);

    // 3) causal GQA flash attention (fp32), writes ctx fp16
    attn_kernel<<<dim3(Tn / 64, NQn, Bn), 256, ATT_SMEM_BYTES>>>(qT, kT, vp, ctxh);

    // 4) output projection (HMMA fp16)
    hgemm_mma<<<dim3(Cn/128, BTn/128), 256>>>(ctxh, woh, out, BTn, Cn, NQn*Hn);
}

// round 8
// speedup vs baseline: 4.5244x; 2.3502x over previous
#include <cuda_runtime.h>
#include <cuda_fp16.h>
#include <cstdint>

// Problem constants
#define Bn   2
#define Tn   2048
#define Cn   2048
#define NQn  16
#define NKVn 4
#define Hn   128
#define BTn  (Bn*Tn)        // 4096
#define SCALE 0.08838834764831845f  // 1/sqrt(128)

// ---------------- scratch (device globals) ------------------------------------
__device__ float  g_qproj[BTn * NQn * Hn];
__device__ float  g_kproj[BTn * NKVn * Hn];
__device__ float  g_vproj[BTn * NKVn * Hn];
__device__ __half g_xh[BTn * Cn];                // x fp16 [M][K]
__device__ __half g_wqh[(NQn*Hn) * Cn];          // W^T fp16 [N][K]
__device__ __half g_wkh[(NKVn*Hn) * Cn];
__device__ __half g_wvh[(NKVn*Hn) * Cn];
__device__ __half g_woh[Cn * (NQn*Hn)];
__device__ __half g_ctxh[BTn * NQn * Hn];        // attention out fp16 [M][K]
__device__ __half g_qh[Bn * NQn * Tn * Hn];      // q fp16 [b][h][t][d]
__device__ __half g_kh[Bn * NKVn * Tn * Hn];     // k fp16 [b][kvh][t][d]
__device__ __half g_vT[Bn * NKVn * Hn * Tn];     // vT fp16 [b][kvh][d][t]

// ---------------- helpers ------------------------------------------------------
__device__ __forceinline__ uint32_t smem_u32(const void* p) {
    uint32_t a;
    asm("{ .reg .u64 t; cvta.to.shared.u64 t, %1; cvt.u32.u64 %0, t; }" : "=r"(a) : "l"(p));
    return a;
}
__device__ __forceinline__ void ldmatrix_x4(uint32_t& r0, uint32_t& r1,
                                            uint32_t& r2, uint32_t& r3, uint32_t addr) {
    asm volatile("ldmatrix.sync.aligned.m8n8.x4.shared.b16 {%0,%1,%2,%3}, [%4];"
                 : "=r"(r0), "=r"(r1), "=r"(r2), "=r"(r3) : "r"(addr));
}
__device__ __forceinline__ void mma16816(float* d, const uint32_t* a, const uint32_t* b) {
    asm volatile(
        "mma.sync.aligned.m16n8k16.row.col.f32.f16.f16.f32 "
        "{%0,%1,%2,%3}, {%4,%5,%6,%7}, {%8,%9}, {%0,%1,%2,%3};"
        : "+f"(d[0]), "+f"(d[1]), "+f"(d[2]), "+f"(d[3])
        : "r"(a[0]), "r"(a[1]), "r"(a[2]), "r"(a[3]), "r"(b[0]), "r"(b[1]));
}

// ---------------- fp32 -> fp16 elementwise ------------------------------------
__global__ void f32_to_f16_kernel(const float* __restrict__ in, __half* __restrict__ out, int n4) {
    int i = blockIdx.x * blockDim.x + threadIdx.x;
    if (i < n4) {
        float4 v = ((const float4*)in)[i];
        ((__half2*)out)[2*i]   = __floats2half2_rn(v.x, v.y);
        ((__half2*)out)[2*i+1] = __floats2half2_rn(v.z, v.w);
    }
}

// ---------------- W [K][N] f32 -> Wt [N][K] f16 (tiled transpose) --------------
__global__ void transpose_to_f16_kernel(const float* __restrict__ W, __half* __restrict__ Wt,
                                        int K, int N) {
    __shared__ float tile[32][33];
    int n0 = blockIdx.x * 32, k0 = blockIdx.y * 32;
    int tx = threadIdx.x, ty = threadIdx.y;   // 32 x 8
    #pragma unroll
    for (int i = 0; i < 32; i += 8)
        tile[ty + i][tx] = W[(size_t)(k0 + ty + i) * N + n0 + tx];
    __syncthreads();
    #pragma unroll
    for (int i = 0; i < 32; i += 8)
        Wt[(size_t)(n0 + ty + i) * K + k0 + tx] = __float2half(tile[tx][ty + i]);
}

// ---------------- vproj [bt][nkv*H] f32 -> vT [b][kvh][d][t] f16 ---------------
__global__ void vtrans_h(const float* __restrict__ vproj, __half* __restrict__ vT) {
    __shared__ float tile[32][33];
    int t0 = blockIdx.x * 32, d0 = blockIdx.y * 32;
    int bk = blockIdx.z; int b = bk / NKVn, kvh = bk % NKVn;
    int tx = threadIdx.x, ty = threadIdx.y;   // 32 x 8
    #pragma unroll
    for (int i = 0; i < 32; i += 8)
        tile[ty + i][tx] = vproj[(size_t)(b * Tn + t0 + ty + i) * (NKVn * Hn) + kvh * Hn + d0 + tx];
    __syncthreads();
    #pragma unroll
    for (int i = 0; i < 32; i += 8)
        vT[((size_t)(b * NKVn + kvh) * Hn + d0 + ty + i) * Tn + t0 + tx] =
            __float2half(tile[tx][ty + i]);
}

// ---------------- HMMA fp16 GEMM: C[M,N]f32 = A[M,K]f16 @ Bt[N,K]f16^T ---------
#define GP 40
__global__ void __launch_bounds__(256) hgemm_mma(const __half* __restrict__ A,
                                                 const __half* __restrict__ B,
                                                 float* __restrict__ C,
                                                 int M, int N, int K) {
    __shared__ __half As[2][128][GP];
    __shared__ __half Bs[2][128][GP];
    int tid = threadIdx.x;
    int lane = tid & 31, wid = tid >> 5;
    int wm = wid >> 2, wn = wid & 3;
    int m0 = blockIdx.y << 7, n0 = blockIdx.x << 7;

    int r0 = tid >> 2, c0 = (tid & 3) * 8;
    int r1 = r0 + 64;
    const __half* Ap0 = A + (size_t)(m0 + r0) * K + c0;
    const __half* Ap1 = A + (size_t)(m0 + r1) * K + c0;
    const __half* Bp0 = B + (size_t)(n0 + r0) * K + c0;
    const __half* Bp1 = B + (size_t)(n0 + r1) * K + c0;

    *(uint4*)&As[0][r0][c0] = *(const uint4*)Ap0;
    *(uint4*)&As[0][r1][c0] = *(const uint4*)Ap1;
    *(uint4*)&Bs[0][r0][c0] = *(const uint4*)Bp0;
    *(uint4*)&Bs[0][r1][c0] = *(const uint4*)Bp1;

    float acc[4][4][4];
    #pragma unroll
    for (int i = 0; i < 4; i++)
        #pragma unroll
        for (int j = 0; j < 4; j++)
            #pragma unroll
            for (int k = 0; k < 4; k++) acc[i][j][k] = 0.f;

    __syncthreads();

    int lrow = lane & 15, lhalf = lane >> 4;
    const int NC = K >> 5;
    uint4 pa0, pa1, pb0, pb1;

    for (int c = 0; c < NC; c++) {
        int cur = c & 1;
        if (c + 1 < NC) {
            pa0 = *(const uint4*)(Ap0 + (c + 1) * 32);
            pa1 = *(const uint4*)(Ap1 + (c + 1) * 32);
            pb0 = *(const uint4*)(Bp0 + (c + 1) * 32);
            pb1 = *(const uint4*)(Bp1 + (c + 1) * 32);
        }

        uint32_t af[4][2][4];
        uint32_t bf[4][2][2];
        #pragma unroll
        for (int mt = 0; mt < 4; mt++) {
            #pragma unroll
            for (int ks = 0; ks < 2; ks++) {
                uint32_t ad = smem_u32(&As[cur][wm*64 + mt*16 + lrow][ks*16 + lhalf*8]);
                ldmatrix_x4(af[mt][ks][0], af[mt][ks][1], af[mt][ks][2], af[mt][ks][3], ad);
            }
        }
        #pragma unroll
        for (int np = 0; np < 2; np++) {
            #pragma unroll
            for (int ks = 0; ks < 2; ks++) {
                uint32_t bd = smem_u32(&Bs[cur][wn*32 + np*16 + lrow][ks*16 + lhalf*8]);
                uint32_t q0, q1, q2, q3;
                ldmatrix_x4(q0, q1, q2, q3, bd);
                bf[np*2+0][ks][0] = q0; bf[np*2+1][ks][0] = q1;
                bf[np*2+0][ks][1] = q2; bf[np*2+1][ks][1] = q3;
            }
        }
        #pragma unroll
        for (int mt = 0; mt < 4; mt++)
            #pragma unroll
            for (int nt = 0; nt < 4; nt++) {
                mma16816(acc[mt][nt], af[mt][0], bf[nt][0]);
                mma16816(acc[mt][nt], af[mt][1], bf[nt][1]);
            }

        if (c + 1 < NC) {
            int nxt = cur ^ 1;
            *(uint4*)&As[nxt][r0][c0] = pa0;
            *(uint4*)&As[nxt][r1][c0] = pa1;
            *(uint4*)&Bs[nxt][r0][c0] = pb0;
            *(uint4*)&Bs[nxt][r1][c0] = pb1;
        }
        __syncthreads();
    }

    int er = lane >> 2, ec = (lane & 3) * 2;
    #pragma unroll
    for (int mt = 0; mt < 4; mt++) {
        int row = m0 + wm*64 + mt*16 + er;
        float* Cr0 = C + (size_t)row * N + n0 + wn*32;
        float* Cr1 = Cr0 + 8 * N;
        #pragma unroll
        for (int nt = 0; nt < 4; nt++) {
            *(float2*)&Cr0[nt*8 + ec] = make_float2(acc[mt][nt][0], acc[mt][nt][1]);
            *(float2*)&Cr1[nt*8 + ec] = make_float2(acc[mt][nt][2], acc[mt][nt][3]);
        }
    }
}

// ---------------- RMSNorm + RoPE -> fp16 [b][h][t][d] --------------------------
__global__ void normrope_h(const float* __restrict__ proj,
                           const float* __restrict__ w,
                           const float* __restrict__ cosb,
                           const float* __restrict__ sinb,
                           __half* __restrict__ outh, int NH) {
    int gw = (blockIdx.x * blockDim.x + threadIdx.x) >> 5;
    int lane = threadIdx.x & 31;
    if (gw >= Bn * Tn * NH) return;
    int h = gw % NH;
    int bt = gw / NH;
    int t = bt % Tn;
    int b = bt / Tn;

    const float* p = proj + (size_t)gw * Hn;
    int d0 = lane * 2;
    float2 xa = *(const float2*)(p + d0);
    float2 xb = *(const float2*)(p + d0 + 64);
    float ss = xa.x*xa.x + xa.y*xa.y + xb.x*xb.x + xb.y*xb.y;
    #pragma unroll
    for (int o = 16; o; o >>= 1) ss += __shfl_xor_sync(0xffffffffu, ss, o);
    float inv = rsqrtf(ss * (1.0f / 128.0f) + 1e-6f);
    float2 wa = *(const float2*)(w + d0);
    float2 wb = *(const float2*)(w + d0 + 64);
    xa.x *= inv * wa.x; xa.y *= inv * wa.y;
    xb.x *= inv * wb.x; xb.y *= inv * wb.y;
    const float* cp = cosb + (size_t)t * Hn;
    const float* sp = sinb + (size_t)t * Hn;
    float2 ca = *(const float2*)(cp + d0), cb = *(const float2*)(cp + d0 + 64);
    float2 sa = *(const float2*)(sp + d0), sb = *(const float2*)(sp + d0 + 64);
    float ya0 = xa.x * ca.x - xb.x * sa.x;
    float ya1 = xa.y * ca.y - xb.y * sa.y;
    float yb0 = xb.x * cb.x + xa.x * sb.x;
    float yb1 = xb.y * cb.y + xa.y * sb.y;
    __half* o = outh + ((size_t)(b * NH + h) * Tn + t) * Hn;
    *(__half2*)(o + d0)      = __floats2half2_rn(ya0, ya1);
    *(__half2*)(o + d0 + 64) = __floats2half2_rn(yb0, yb1);
}

// ---------------- HMMA flash attention (causal, GQA) ---------------------------
// CTA: 128 q-rows, 8 warps x 16 rows; kv tiles of 64.
#define AKP 136   // Q/K smem row pitch (halfs)
#define AVP 72    // Vt smem row pitch (halfs)
__global__ void __launch_bounds__(256) attn_mma(const __half* __restrict__ qh,
                                                const __half* __restrict__ kh,
                                                const __half* __restrict__ vT,
                                                __half* __restrict__ ctxh) {
    __shared__ __align__(16) __half smem_[64 * AKP + 128 * AVP];  // 17920 halfs
    __half* Ks = smem_;
    __half* Vs = smem_ + 64 * AKP;
    __half* Qs = smem_;   // Q staging overlaps (128*AKP = 17408 <= 17920)

    int tid = threadIdx.x, lane = tid & 31, w = tid >> 5;
    int q0 = blockIdx.x << 7;
    int h = blockIdx.y, b = blockIdx.z;
    int kvh = h >> 2;

    const __half* qb = qh + ((size_t)(b * NQn + h) * Tn + q0) * Hn;
    const __half* kb = kh + (size_t)(b * NKVn + kvh) * Tn * Hn;
    const __half* vb = vT + (size_t)(b * NKVn + kvh) * Hn * Tn;

    // stage Q [128][128] -> regs
    #pragma unroll
    for (int i = 0; i < 8; i++) {
        int f = tid + i * 256; int r = f >> 4, c8 = (f & 15) << 3;
        *(uint4*)&Qs[r * AKP + c8] = *(const uint4*)(qb + (size_t)r * Hn + c8);
    }
    __syncthreads();
    int lrow = lane & 15, lhalf = lane >> 4;
    uint32_t qf[8][4];
    #pragma unroll
    for (int ks = 0; ks < 8; ks++) {
        uint32_t ad = smem_u32(&Qs[(w * 16 + lrow) * AKP + ks * 16 + lhalf * 8]);
        ldmatrix_x4(qf[ks][0], qf[ks][1], qf[ks][2], qf[ks][3], ad);
    }
    __syncthreads();

    float oacc[16][4];
    #pragma unroll
    for (int i = 0; i < 16; i++) { oacc[i][0]=0.f; oacc[i][1]=0.f; oacc[i][2]=0.f; oacc[i][3]=0.f; }
    float m0 = -1e30f, m1 = -1e30f, l0 = 0.f, l1 = 0.f;
    int ec = (lane & 3) * 2;
    int r0 = q0 + w * 16 + (lane >> 2);
    int r1 = r0 + 8;

    for (int j0 = 0; j0 <= q0 + 64; j0 += 64) {
        #pragma unroll
        for (int i = 0; i < 4; i++) {
            int f = tid + i * 256; int r = f >> 4, c8 = (f & 15) << 3;
            *(uint4*)&Ks[r * AKP + c8] = *(const uint4*)(kb + (size_t)(j0 + r) * Hn + c8);
        }
        #pragma unroll
        for (int i = 0; i < 4; i++) {
            int f = tid + i * 256; int r = f >> 3, c8 = (f & 7) << 3;
            *(uint4*)&Vs[r * AVP + c8] = *(const uint4*)(vb + (size_t)r * Tn + j0 + c8);
        }
        __syncthreads();

        // S = Q @ K^T
        float sacc[8][4];
        #pragma unroll
        for (int i = 0; i < 8; i++) { sacc[i][0]=0.f; sacc[i][1]=0.f; sacc[i][2]=0.f; sacc[i][3]=0.f; }
        #pragma unroll
        for (int ks = 0; ks < 8; ks++) {
            #pragma unroll
            for (int np = 0; np < 4; np++) {
                uint32_t ad = smem_u32(&Ks[(np * 16 + lrow) * AKP + ks * 16 + lhalf * 8]);
                uint32_t t0, t1, t2, t3;
                ldmatrix_x4(t0, t1, t2, t3, ad);
                uint32_t b0[2] = {t0, t2}, b1[2] = {t1, t3};
                mma16816(sacc[np * 2],     qf[ks], b0);
                mma16816(sacc[np * 2 + 1], qf[ks], b1);
            }
        }

        // scale + causal mask
        #pragma unroll
        for (int nt = 0; nt < 8; nt++) {
            int c = j0 + nt * 8 + ec;
            sacc[nt][0] = (c     > r0) ? -1e30f : sacc[nt][0] * SCALE;
            sacc[nt][1] = (c + 1 > r0) ? -1e30f : sacc[nt][1] * SCALE;
            sacc[nt][2] = (c     > r1) ? -1e30f : sacc[nt][2] * SCALE;
            sacc[nt][3] = (c + 1 > r1) ? -1e30f : sacc[nt][3] * SCALE;
        }

        // online softmax (rows r0, r1); quad = lanes sharing a row (xor 1,2)
        float tm0 = -1e30f, tm1 = -1e30f;
        #pragma unroll
        for (int nt = 0; nt < 8; nt++) {
            tm0 = fmaxf(tm0, fmaxf(sacc[nt][0], sacc[nt][1]));
            tm1 = fmaxf(tm1, fmaxf(sacc[nt][2], sacc[nt][3]));
        }
        tm0 = fmaxf(tm0, __shfl_xor_sync(0xffffffffu, tm0, 1));
        tm0 = fmaxf(tm0, __shfl_xor_sync(0xffffffffu, tm0, 2));
        tm1 = fmaxf(tm1, __shfl_xor_sync(0xffffffffu, tm1, 1));
        tm1 = fmaxf(tm1, __shfl_xor_sync(0xffffffffu, tm1, 2));
        float mn0 = fmaxf(m0, tm0), mn1 = fmaxf(m1, tm1);
        float al0 = __expf(m0 - mn0), al1 = __expf(m1 - mn1);
        m0 = mn0; m1 = mn1;

        float rs0 = 0.f, rs1 = 0.f;
        uint32_t pf[4][4];
        #pragma unroll
        for (int nt = 0; nt < 8; nt++) {
            float p0 = __expf(sacc[nt][0] - mn0);
            float p1 = __expf(sacc[nt][1] - mn0);
            float p2 = __expf(sacc[nt][2] - mn1);
            float p3 = __expf(sacc[nt][3] - mn1);
            rs0 += p0 + p1; rs1 += p2 + p3;
            __half2 v01 = __floats2half2_rn(p0, p1);
            __half2 v23 = __floats2half2_rn(p2, p3);
            int kt = nt >> 1;
            if ((nt & 1) == 0) {
                pf[kt][0] = *(uint32_t*)&v01;
                pf[kt][1] = *(uint32_t*)&v23;
            } else {
                pf[kt][2] = *(uint32_t*)&v01;
                pf[kt][3] = *(uint32_t*)&v23;
            }
        }
        rs0 += __shfl_xor_sync(0xffffffffu, rs0, 1);
        rs0 += __shfl_xor_sync(0xffffffffu, rs0, 2);
        rs1 += __shfl_xor_sync(0xffffffffu, rs1, 1);
        rs1 += __shfl_xor_sync(0xffffffffu, rs1, 2);
        l0 = l0 * al0 + rs0;
        l1 = l1 * al1 + rs1;

        #pragma unroll
        for (int dt = 0; dt < 16; dt++) {
            oacc[dt][0] *= al0; oacc[dt][1] *= al0;
            oacc[dt][2] *= al1; oacc[dt][3] *= al1;
        }

        // O += P @ V   (V^T tiles are the col-major B operand)
        #pragma unroll
        for (int kt = 0; kt < 4; kt++) {
            #pragma unroll
            for (int np = 0; np < 8; np++) {
                uint32_t ad = smem_u32(&Vs[(np * 16 + lrow) * AVP + kt * 16 + lhalf * 8]);
                uint32_t t0, t1, t2, t3;
                ldmatrix_x4(t0, t1, t2, t3, ad);
                uint32_t b0[2] = {t0, t2}, b1[2] = {t1, t3};
                mma16816(oacc[np * 2],     pf[kt], b0);
                mma16816(oacc[np * 2 + 1], pf[kt], b1);
            }
        }
        __syncthreads();
    }

    // epilogue
    float inv0 = 1.0f / l0, inv1 = 1.0f / l1;
    __half* o0 = ctxh + (size_t)(b * Tn + r0) * (NQn * Hn) + h * Hn;
    __half* o1 = ctxh + (size_t)(b * Tn + r1) * (NQn * Hn) + h * Hn;
    #pragma unroll
    for (int dt = 0; dt < 16; dt++) {
        __half2 w0 = __floats2half2_rn(oacc[dt][0] * inv0, oacc[dt][1] * inv0);
        __half2 w1 = __floats2half2_rn(oacc[dt][2] * inv1, oacc[dt][3] * inv1);
        *(__half2*)&o0[dt * 8 + ec] = w0;
        *(__half2*)&o1[dt * 8 + ec] = w1;
    }
}

// ---------------- launch ------------------------------------------------------
extern "C" void kernel_launch(void* const* d_in, const int* in_sizes, int n_in,
                              void* d_out, int out_size) {
    (void)in_sizes; (void)n_in; (void)out_size;
    const float* x   = (const float*)d_in[0];
    const float* Wq  = (const float*)d_in[1];
    const float* Wk  = (const float*)d_in[2];
    const float* Wv  = (const float*)d_in[3];
    const float* Wo  = (const float*)d_in[4];
    const float* qnw = (const float*)d_in[5];
    const float* knw = (const float*)d_in[6];
    const float* cosb = (const float*)d_in[7];
    const float* sinb = (const float*)d_in[8];
    float* out = (float*)d_out;

    float *qp, *kp, *vp;
    __half *xh, *wqh, *wkh, *wvh, *woh, *ctxh, *qh, *kh, *vT;
    cudaGetSymbolAddress((void**)&qp,  g_qproj);
    cudaGetSymbolAddress((void**)&kp,  g_kproj);
    cudaGetSymbolAddress((void**)&vp,  g_vproj);
    cudaGetSymbolAddress((void**)&xh,  g_xh);
    cudaGetSymbolAddress((void**)&wqh, g_wqh);
    cudaGetSymbolAddress((void**)&wkh, g_wkh);
    cudaGetSymbolAddress((void**)&wvh, g_wvh);
    cudaGetSymbolAddress((void**)&woh, g_woh);
    cudaGetSymbolAddress((void**)&ctxh, g_ctxh);
    cudaGetSymbolAddress((void**)&qh,  g_qh);
    cudaGetSymbolAddress((void**)&kh,  g_kh);
    cudaGetSymbolAddress((void**)&vT,  g_vT);

    // 0) conversions
    f32_to_f16_kernel<<<(BTn * Cn / 4 + 255) / 256, 256>>>(x, xh, BTn * Cn / 4);
    transpose_to_f16_kernel<<<dim3((NQn*Hn)/32, Cn/32), dim3(32, 8)>>>(Wq, wqh, Cn, NQn*Hn);
    transpose_to_f16_kernel<<<dim3((NKVn*Hn)/32, Cn/32), dim3(32, 8)>>>(Wk, wkh, Cn, NKVn*Hn);
    transpose_to_f16_kernel<<<dim3((NKVn*Hn)/32, Cn/32), dim3(32, 8)>>>(Wv, wvh, Cn, NKVn*Hn);
    transpose_to_f16_kernel<<<dim3(Cn/32, (NQn*Hn)/32), dim3(32, 8)>>>(Wo, woh, NQn*Hn, Cn);

    // 1) projections (HMMA fp16)
    hgemm_mma<<<dim3((NQn*Hn)/128, BTn/128), 256>>>(xh, wqh, qp, BTn, NQn*Hn, Cn);
    hgemm_mma<<<dim3((NKVn*Hn)/128, BTn/128), 256>>>(xh, wkh, kp, BTn, NKVn*Hn, Cn);
    hgemm_mma<<<dim3((NKVn*Hn)/128, BTn/128), 256>>>(xh, wvh, vp, BTn, NKVn*Hn, Cn);

    // 2) rmsnorm + rope -> fp16 [b][h][t][d]; V -> fp16 transposed [b][kvh][d][t]
    normrope_h<<<(Bn * Tn * NQn) / 8, 256>>>(qp, qnw, cosb, sinb, qh, NQn);
    normrope_h<<<(Bn * Tn * NKVn) / 8, 256>>>(kp, knw, cosb, sinb, kh, NKVn);
    vtrans_h<<<dim3(Tn/32, Hn/32, Bn*NKVn), dim3(32, 8)>>>(vp, vT);

    // 3) causal GQA flash attention (HMMA fp16), writes ctx fp16
    attn_mma<<<dim3(Tn / 128, NQn, Bn), 256>>>(qh, kh, vT, ctxh);

    // 4) output projection (HMMA fp16)
    hgemm_mma<<<dim3(Cn/128, BTn/128), 256>>>(ctxh, woh, out, BTn, Cn, NQn*Hn);
}

// round 9
// speedup vs baseline: 5.1100x; 1.1294x over previous
#include <cuda_runtime.h>
#include <cuda_fp16.h>
#include <cstdint>

// Problem constants
#define Bn   2
#define Tn   2048
#define Cn   2048
#define NQn  16
#define NKVn 4
#define Hn   128
#define BTn  (Bn*Tn)        // 4096
#define NQKV 3072           // 2048 q + 512 k + 512 v
#define SCALE 0.08838834764831845f  // 1/sqrt(128)

// ---------------- scratch (device globals) ------------------------------------
__device__ float  g_qkv[BTn * NQKV];             // fused qkv proj f32 [bt][3072]
__device__ __half g_xh[BTn * Cn];                // x fp16 [M][K]
__device__ __half g_wqkvh[NQKV * Cn];            // [Wq^T; Wk^T; Wv^T] fp16 [3072][2048]
__device__ __half g_woh[Cn * (NQn*Hn)];          // Wo^T fp16 [2048][2048]
__device__ __half g_ctxh[BTn * NQn * Hn];        // attention out fp16
__device__ __half g_qh[Bn * NQn * Tn * Hn];      // q fp16 [b][h][t][d]
__device__ __half g_kh[Bn * NKVn * Tn * Hn];     // k fp16 [b][kvh][t][d]
__device__ __half g_vT[Bn * NKVn * Hn * Tn];     // vT fp16 [b][kvh][d][t]

// ---------------- helpers ------------------------------------------------------
__device__ __forceinline__ uint32_t smem_u32(const void* p) {
    uint32_t a;
    asm("{ .reg .u64 t; cvta.to.shared.u64 t, %1; cvt.u32.u64 %0, t; }" : "=r"(a) : "l"(p));
    return a;
}
__device__ __forceinline__ void ldmatrix_x4(uint32_t& r0, uint32_t& r1,
                                            uint32_t& r2, uint32_t& r3, uint32_t addr) {
    asm volatile("ldmatrix.sync.aligned.m8n8.x4.shared.b16 {%0,%1,%2,%3}, [%4];"
                 : "=r"(r0), "=r"(r1), "=r"(r2), "=r"(r3) : "r"(addr));
}
__device__ __forceinline__ void mma16816(float* d, const uint32_t* a, const uint32_t* b) {
    asm volatile(
        "mma.sync.aligned.m16n8k16.row.col.f32.f16.f16.f32 "
        "{%0,%1,%2,%3}, {%4,%5,%6,%7}, {%8,%9}, {%0,%1,%2,%3};"
        : "+f"(d[0]), "+f"(d[1]), "+f"(d[2]), "+f"(d[3])
        : "r"(a[0]), "r"(a[1]), "r"(a[2]), "r"(a[3]), "r"(b[0]), "r"(b[1]));
}
__device__ __forceinline__ void cp16(uint32_t dst, const void* src) {
    asm volatile("cp.async.cg.shared.global [%0], [%1], 16;"
                 :: "r"(dst), "l"(__cvta_generic_to_global(src)));
}
#define CP_COMMIT() asm volatile("cp.async.commit_group;")

// ---------------- fp32 -> fp16 elementwise ------------------------------------
__global__ void f32_to_f16_kernel(const float* __restrict__ in, __half* __restrict__ out, int n4) {
    int i = blockIdx.x * blockDim.x + threadIdx.x;
    if (i < n4) {
        float4 v = ((const float4*)in)[i];
        ((__half2*)out)[2*i]   = __floats2half2_rn(v.x, v.y);
        ((__half2*)out)[2*i+1] = __floats2half2_rn(v.z, v.w);
    }
}

// ---------------- W [K][N] f32 -> Wt [N][K] f16 (tiled transpose) --------------
__global__ void transpose_to_f16_kernel(const float* __restrict__ W, __half* __restrict__ Wt,
                                        int K, int N) {
    __shared__ float tile[32][33];
    int n0 = blockIdx.x * 32, k0 = blockIdx.y * 32;
    int tx = threadIdx.x, ty = threadIdx.y;   // 32 x 8
    #pragma unroll
    for (int i = 0; i < 32; i += 8)
        tile[ty + i][tx] = W[(size_t)(k0 + ty + i) * N + n0 + tx];
    __syncthreads();
    #pragma unroll
    for (int i = 0; i < 32; i += 8)
        Wt[(size_t)(n0 + ty + i) * K + k0 + tx] = __float2half(tile[tx][ty + i]);
}

// ---------------- qkv [bt][3072] f32 (v at col 2560) -> vT [b][kvh][d][t] f16 --
__global__ void vtrans_h(const float* __restrict__ qkv, __half* __restrict__ vT) {
    __shared__ float tile[32][33];
    int t0 = blockIdx.x * 32, d0 = blockIdx.y * 32;
    int bk = blockIdx.z; int b = bk / NKVn, kvh = bk % NKVn;
    int tx = threadIdx.x, ty = threadIdx.y;   // 32 x 8
    #pragma unroll
    for (int i = 0; i < 32; i += 8)
        tile[ty + i][tx] =
            qkv[(size_t)(b * Tn + t0 + ty + i) * NQKV + 2560 + kvh * Hn + d0 + tx];
    __syncthreads();
    #pragma unroll
    for (int i = 0; i < 32; i += 8)
        vT[((size_t)(b * NKVn + kvh) * Hn + d0 + ty + i) * Tn + t0 + tx] =
            __float2half(tile[tx][ty + i]);
}

// ---------------- HMMA GEMM, 4-stage cp.async pipeline -------------------------
// C[M,N]f32 = A[M,K]f16 @ Bt[N,K]f16^T ; CTA 128x128, K-chunk 32.
#define GP 40
#define GSTG 4
#define G_AH (128*GP)             // halfs per operand tile (5120)
#define G_STAGE_H (2*G_AH)        // halfs per stage (10240)
#define G_SMEM_B (GSTG * G_STAGE_H * 2)   // 81920 bytes
__global__ void __launch_bounds__(256) hgemm_pipe(const __half* __restrict__ A,
                                                  const __half* __restrict__ B,
                                                  float* __restrict__ C,
                                                  int M, int N, int K) {
    extern __shared__ __half hsm[];
    uint32_t smb = smem_u32(hsm);
    int tid = threadIdx.x;
    int lane = tid & 31, wid = tid >> 5;
    int wm = wid >> 2, wn = wid & 3;
    int m0 = blockIdx.y << 7, n0 = blockIdx.x << 7;

    int r0 = tid >> 2, c0 = (tid & 3) * 8;
    int r1 = r0 + 64;
    const __half* Ap0 = A + (size_t)(m0 + r0) * K + c0;
    const __half* Ap1 = A + (size_t)(m0 + r1) * K + c0;
    const __half* Bp0 = B + (size_t)(n0 + r0) * K + c0;
    const __half* Bp1 = B + (size_t)(n0 + r1) * K + c0;

    const int NC = K >> 5;

    auto issue = [&](int c) {
        int s = c & (GSTG - 1);
        uint32_t base = smb + s * (G_STAGE_H * 2);
        cp16(base + (r0 * GP + c0) * 2,          Ap0 + c * 32);
        cp16(base + (r1 * GP + c0) * 2,          Ap1 + c * 32);
        cp16(base + (G_AH + r0 * GP + c0) * 2,   Bp0 + c * 32);
        cp16(base + (G_AH + r1 * GP + c0) * 2,   Bp1 + c * 32);
        CP_COMMIT();
    };

    #pragma unroll
    for (int s = 0; s < GSTG - 1; s++) issue(s);

    float acc[4][4][4];
    #pragma unroll
    for (int i = 0; i < 4; i++)
        #pragma unroll
        for (int j = 0; j < 4; j++)
            #pragma unroll
            for (int k = 0; k < 4; k++) acc[i][j][k] = 0.f;

    int lrow = lane & 15, lhalf = lane >> 4;

    for (int c = 0; c < NC; c++) {
        asm volatile("cp.async.wait_group %0;" :: "n"(GSTG - 2));
        __syncthreads();
        if (c + GSTG - 1 < NC) issue(c + GSTG - 1);

        uint32_t sbase = smb + (c & (GSTG - 1)) * (G_STAGE_H * 2);
        uint32_t af[4][2][4];
        uint32_t bf[4][2][2];
        #pragma unroll
        for (int mt = 0; mt < 4; mt++) {
            #pragma unroll
            for (int ks = 0; ks < 2; ks++) {
                uint32_t ad = sbase + ((wm*64 + mt*16 + lrow) * GP + ks*16 + lhalf*8) * 2;
                ldmatrix_x4(af[mt][ks][0], af[mt][ks][1], af[mt][ks][2], af[mt][ks][3], ad);
            }
        }
        #pragma unroll
        for (int np = 0; np < 2; np++) {
            #pragma unroll
            for (int ks = 0; ks < 2; ks++) {
                uint32_t bd = sbase + (G_AH + (wn*32 + np*16 + lrow) * GP + ks*16 + lhalf*8) * 2;
                uint32_t q0, q1, q2, q3;
                ldmatrix_x4(q0, q1, q2, q3, bd);
                bf[np*2+0][ks][0] = q0; bf[np*2+1][ks][0] = q1;
                bf[np*2+0][ks][1] = q2; bf[np*2+1][ks][1] = q3;
            }
        }
        #pragma unroll
        for (int mt = 0; mt < 4; mt++)
            #pragma unroll
            for (int nt = 0; nt < 4; nt++) {
                mma16816(acc[mt][nt], af[mt][0], bf[nt][0]);
                mma16816(acc[mt][nt], af[mt][1], bf[nt][1]);
            }
    }

    int er = lane >> 2, ec = (lane & 3) * 2;
    #pragma unroll
    for (int mt = 0; mt < 4; mt++) {
        int row = m0 + wm*64 + mt*16 + er;
        float* Cr0 = C + (size_t)row * N + n0 + wn*32;
        float* Cr1 = Cr0 + 8 * N;
        #pragma unroll
        for (int nt = 0; nt < 4; nt++) {
            *(float2*)&Cr0[nt*8 + ec] = make_float2(acc[mt][nt][0], acc[mt][nt][1]);
            *(float2*)&Cr1[nt*8 + ec] = make_float2(acc[mt][nt][2], acc[mt][nt][3]);
        }
    }
}

// ---------------- RMSNorm + RoPE -> fp16 [b][h][t][d] --------------------------
__global__ void normrope_h(const float* __restrict__ proj, int stride, int coloff,
                           const float* __restrict__ w,
                           const float* __restrict__ cosb,
                           const float* __restrict__ sinb,
                           __half* __restrict__ outh, int NH) {
    int gw = (blockIdx.x * blockDim.x + threadIdx.x) >> 5;
    int lane = threadIdx.x & 31;
    if (gw >= Bn * Tn * NH) return;
    int h = gw % NH;
    int bt = gw / NH;
    int t = bt % Tn;
    int b = bt / Tn;

    const float* p = proj + (size_t)bt * stride + coloff + h * Hn;
    int d0 = lane * 2;
    float2 xa = *(const float2*)(p + d0);
    float2 xb = *(const float2*)(p + d0 + 64);
    float ss = xa.x*xa.x + xa.y*xa.y + xb.x*xb.x + xb.y*xb.y;
    #pragma unroll
    for (int o = 16; o; o >>= 1) ss += __shfl_xor_sync(0xffffffffu, ss, o);
    float inv = rsqrtf(ss * (1.0f / 128.0f) + 1e-6f);
    float2 wa = *(const float2*)(w + d0);
    float2 wb = *(const float2*)(w + d0 + 64);
    xa.x *= inv * wa.x; xa.y *= inv * wa.y;
    xb.x *= inv * wb.x; xb.y *= inv * wb.y;
    const float* cp = cosb + (size_t)t * Hn;
    const float* sp = sinb + (size_t)t * Hn;
    float2 ca = *(const float2*)(cp + d0), cb = *(const float2*)(cp + d0 + 64);
    float2 sa = *(const float2*)(sp + d0), sb = *(const float2*)(sp + d0 + 64);
    float ya0 = xa.x * ca.x - xb.x * sa.x;
    float ya1 = xa.y * ca.y - xb.y * sa.y;
    float yb0 = xb.x * cb.x + xa.x * sb.x;
    float yb1 = xb.y * cb.y + xa.y * sb.y;
    __half* o = outh + ((size_t)(b * NH + h) * Tn + t) * Hn;
    *(__half2*)(o + d0)      = __floats2half2_rn(ya0, ya1);
    *(__half2*)(o + d0 + 64) = __floats2half2_rn(yb0, yb1);
}

// ---------------- HMMA flash attention (causal, GQA), cp.async 2-stage ---------
#define AKP 136   // K smem row pitch (halfs)
#define AVP 72    // Vt smem row pitch (halfs)
#define A_KB (64 * AKP)               // K tile halfs (8704)
#define A_STAGE_H (A_KB + 128 * AVP)  // stage halfs (17920)
#define A_SMEM_B (2 * A_STAGE_H * 2)  // 71680 bytes
__global__ void __launch_bounds__(256) attn_mma(const __half* __restrict__ qh,
                                                const __half* __restrict__ kh,
                                                const __half* __restrict__ vT,
                                                __half* __restrict__ ctxh) {
    extern __shared__ __half asm_[];
    uint32_t smb = smem_u32(asm_);

    int tid = threadIdx.x, lane = tid & 31, w = tid >> 5;
    int q0 = blockIdx.x << 7;
    int h = blockIdx.y, b = blockIdx.z;
    int kvh = h >> 2;

    const __half* qb = qh + ((size_t)(b * NQn + h) * Tn + q0) * Hn;
    const __half* kb = kh + (size_t)(b * NKVn + kvh) * Tn * Hn;
    const __half* vb = vT + (size_t)(b * NKVn + kvh) * Hn * Tn;

    // stage Q [128][128] into smem (AKP pitch), extract fragments
    #pragma unroll
    for (int i = 0; i < 8; i++) {
        int f = tid + i * 256; int r = f >> 4, c8 = (f & 15) << 3;
        *(uint4*)&asm_[r * AKP + c8] = *(const uint4*)(qb + (size_t)r * Hn + c8);
    }
    __syncthreads();
    int lrow = lane & 15, lhalf = lane >> 4;
    uint32_t qf[8][4];
    #pragma unroll
    for (int ks = 0; ks < 8; ks++) {
        uint32_t ad = smb + ((w * 16 + lrow) * AKP + ks * 16 + lhalf * 8) * 2;
        ldmatrix_x4(qf[ks][0], qf[ks][1], qf[ks][2], qf[ks][3], ad);
    }
    __syncthreads();

    auto issue_kv = [&](int jt) {
        int st = jt & 1;
        uint32_t base = smb + st * (A_STAGE_H * 2);
        int j0 = jt << 6;
        #pragma unroll
        for (int i = 0; i < 4; i++) {
            int f = tid + i * 256; int r = f >> 4, c8 = (f & 15) << 3;
            cp16(base + (r * AKP + c8) * 2, kb + (size_t)(j0 + r) * Hn + c8);
        }
        #pragma unroll
        for (int i = 0; i < 4; i++) {
            int f = tid + i * 256; int r = f >> 3, c8 = (f & 7) << 3;
            cp16(base + (A_KB + r * AVP + c8) * 2, vb + (size_t)r * Tn + j0 + c8);
        }
        CP_COMMIT();
    };

    const int NT = (q0 >> 6) + 2;
    issue_kv(0);

    float oacc[16][4];
    #pragma unroll
    for (int i = 0; i < 16; i++) { oacc[i][0]=0.f; oacc[i][1]=0.f; oacc[i][2]=0.f; oacc[i][3]=0.f; }
    float m0 = -1e30f, m1 = -1e30f, l0 = 0.f, l1 = 0.f;
    int ec = (lane & 3) * 2;
    int r0 = q0 + w * 16 + (lane >> 2);
    int r1 = r0 + 8;

    for (int jt = 0; jt < NT; jt++) {
        int j0 = jt << 6;
        if (jt + 1 < NT) {
            issue_kv(jt + 1);
            asm volatile("cp.async.wait_group 1;");
        } else {
            asm volatile("cp.async.wait_group 0;");
        }
        __syncthreads();
        uint32_t sbase = smb + (jt & 1) * (A_STAGE_H * 2);

        // S = Q @ K^T
        float sacc[8][4];
        #pragma unroll
        for (int i = 0; i < 8; i++) { sacc[i][0]=0.f; sacc[i][1]=0.f; sacc[i][2]=0.f; sacc[i][3]=0.f; }
        #pragma unroll
        for (int ks = 0; ks < 8; ks++) {
            #pragma unroll
            for (int np = 0; np < 4; np++) {
                uint32_t ad = sbase + ((np * 16 + lrow) * AKP + ks * 16 + lhalf * 8) * 2;
                uint32_t t0, t1, t2, t3;
                ldmatrix_x4(t0, t1, t2, t3, ad);
                uint32_t b0[2] = {t0, t2}, b1[2] = {t1, t3};
                mma16816(sacc[np * 2],     qf[ks], b0);
                mma16816(sacc[np * 2 + 1], qf[ks], b1);
            }
        }

        // scale + causal mask
        #pragma unroll
        for (int nt = 0; nt < 8; nt++) {
            int c = j0 + nt * 8 + ec;
            sacc[nt][0] = (c     > r0) ? -1e30f : sacc[nt][0] * SCALE;
            sacc[nt][1] = (c + 1 > r0) ? -1e30f : sacc[nt][1] * SCALE;
            sacc[nt][2] = (c     > r1) ? -1e30f : sacc[nt][2] * SCALE;
            sacc[nt][3] = (c + 1 > r1) ? -1e30f : sacc[nt][3] * SCALE;
        }

        // online softmax (rows r0, r1)
        float tm0 = -1e30f, tm1 = -1e30f;
        #pragma unroll
        for (int nt = 0; nt < 8; nt++) {
            tm0 = fmaxf(tm0, fmaxf(sacc[nt][0], sacc[nt][1]));
            tm1 = fmaxf(tm1, fmaxf(sacc[nt][2], sacc[nt][3]));
        }
        tm0 = fmaxf(tm0, __shfl_xor_sync(0xffffffffu, tm0, 1));
        tm0 = fmaxf(tm0, __shfl_xor_sync(0xffffffffu, tm0, 2));
        tm1 = fmaxf(tm1, __shfl_xor_sync(0xffffffffu, tm1, 1));
        tm1 = fmaxf(tm1, __shfl_xor_sync(0xffffffffu, tm1, 2));
        float mn0 = fmaxf(m0, tm0), mn1 = fmaxf(m1, tm1);
        float al0 = __expf(m0 - mn0), al1 = __expf(m1 - mn1);
        m0 = mn0; m1 = mn1;

        float rs0 = 0.f, rs1 = 0.f;
        uint32_t pf[4][4];
        #pragma unroll
        for (int nt = 0; nt < 8; nt++) {
            float p0 = __expf(sacc[nt][0] - mn0);
            float p1 = __expf(sacc[nt][1] - mn0);
            float p2 = __expf(sacc[nt][2] - mn1);
            float p3 = __expf(sacc[nt][3] - mn1);
            rs0 += p0 + p1; rs1 += p2 + p3;
            __half2 v01 = __floats2half2_rn(p0, p1);
            __half2 v23 = __floats2half2_rn(p2, p3);
            int kt = nt >> 1;
            if ((nt & 1) == 0) {
                pf[kt][0] = *(uint32_t*)&v01;
                pf[kt][1] = *(uint32_t*)&v23;
            } else {
                pf[kt][2] = *(uint32_t*)&v01;
                pf[kt][3] = *(uint32_t*)&v23;
            }
        }
        rs0 += __shfl_xor_sync(0xffffffffu, rs0, 1);
        rs0 += __shfl_xor_sync(0xffffffffu, rs0, 2);
        rs1 += __shfl_xor_sync(0xffffffffu, rs1, 1);
        rs1 += __shfl_xor_sync(0xffffffffu, rs1, 2);
        l0 = l0 * al0 + rs0;
        l1 = l1 * al1 + rs1;

        #pragma unroll
        for (int dt = 0; dt < 16; dt++) {
            oacc[dt][0] *= al0; oacc[dt][1] *= al0;
            oacc[dt][2] *= al1; oacc[dt][3] *= al1;
        }

        // O += P @ V
        #pragma unroll
        for (int kt = 0; kt < 4; kt++) {
            #pragma unroll
            for (int np = 0; np < 8; np++) {
                uint32_t ad = sbase + (A_KB + (np * 16 + lrow) * AVP + kt * 16 + lhalf * 8) * 2;
                uint32_t t0, t1, t2, t3;
                ldmatrix_x4(t0, t1, t2, t3, ad);
                uint32_t b0[2] = {t0, t2}, b1[2] = {t1, t3};
                mma16816(oacc[np * 2],     pf[kt], b0);
                mma16816(oacc[np * 2 + 1], pf[kt], b1);
            }
        }
        __syncthreads();
    }

    // epilogue
    float inv0 = 1.0f / l0, inv1 = 1.0f / l1;
    __half* o0 = ctxh + (size_t)(b * Tn + r0) * (NQn * Hn) + h * Hn;
    __half* o1 = ctxh + (size_t)(b * Tn + r1) * (NQn * Hn) + h * Hn;
    #pragma unroll
    for (int dt = 0; dt < 16; dt++) {
        __half2 w0 = __floats2half2_rn(oacc[dt][0] * inv0, oacc[dt][1] * inv0);
        __half2 w1 = __floats2half2_rn(oacc[dt][2] * inv1, oacc[dt][3] * inv1);
        *(__half2*)&o0[dt * 8 + ec] = w0;
        *(__half2*)&o1[dt * 8 + ec] = w1;
    }
}

// ---------------- launch ------------------------------------------------------
extern "C" void kernel_launch(void* const* d_in, const int* in_sizes, int n_in,
                              void* d_out, int out_size) {
    (void)in_sizes; (void)n_in; (void)out_size;
    const float* x   = (const float*)d_in[0];
    const float* Wq  = (const float*)d_in[1];
    const float* Wk  = (const float*)d_in[2];
    const float* Wv  = (const float*)d_in[3];
    const float* Wo  = (const float*)d_in[4];
    const float* qnw = (const float*)d_in[5];
    const float* knw = (const float*)d_in[6];
    const float* cosb = (const float*)d_in[7];
    const float* sinb = (const float*)d_in[8];
    float* out = (float*)d_out;

    float *qkv;
    __half *xh, *wqkvh, *woh, *ctxh, *qh, *kh, *vT;
    cudaGetSymbolAddress((void**)&qkv,   g_qkv);
    cudaGetSymbolAddress((void**)&xh,    g_xh);
    cudaGetSymbolAddress((void**)&wqkvh, g_wqkvh);
    cudaGetSymbolAddress((void**)&woh,   g_woh);
    cudaGetSymbolAddress((void**)&ctxh,  g_ctxh);
    cudaGetSymbolAddress((void**)&qh,    g_qh);
    cudaGetSymbolAddress((void**)&kh,    g_kh);
    cudaGetSymbolAddress((void**)&vT,    g_vT);

    cudaFuncSetAttribute(hgemm_pipe, cudaFuncAttributeMaxDynamicSharedMemorySize, G_SMEM_B);
    cudaFuncSetAttribute(attn_mma,   cudaFuncAttributeMaxDynamicSharedMemorySize, A_SMEM_B);

    // 0) weight transposes into fused layout (launches 1-4), x conversion (5)
    transpose_to_f16_kernel<<<dim3((NQn*Hn)/32, Cn/32), dim3(32, 8)>>>(Wq, wqkvh, Cn, NQn*Hn);
    transpose_to_f16_kernel<<<dim3((NKVn*Hn)/32, Cn/32), dim3(32, 8)>>>(Wk, wqkvh + (size_t)2048*Cn, Cn, NKVn*Hn);
    transpose_to_f16_kernel<<<dim3((NKVn*Hn)/32, Cn/32), dim3(32, 8)>>>(Wv, wqkvh + (size_t)2560*Cn, Cn, NKVn*Hn);
    transpose_to_f16_kernel<<<dim3(Cn/32, (NQn*Hn)/32), dim3(32, 8)>>>(Wo, woh, NQn*Hn, Cn);
    f32_to_f16_kernel<<<(BTn * Cn / 4 + 255) / 256, 256>>>(x, xh, BTn * Cn / 4);

    // 1) fused QKV projection (launch 6 — ncu capture target)
    hgemm_pipe<<<dim3(NQKV/128, BTn/128), 256, G_SMEM_B>>>(xh, wqkvh, qkv, BTn, NQKV, Cn);

    // 2) rmsnorm + rope -> fp16 [b][h][t][d]; V -> fp16 transposed [b][kvh][d][t]
    normrope_h<<<(Bn * Tn * NQn) / 8, 256>>>(qkv, NQKV, 0,    qnw, cosb, sinb, qh, NQn);
    normrope_h<<<(Bn * Tn * NKVn) / 8, 256>>>(qkv, NQKV, 2048, knw, cosb, sinb, kh, NKVn);
    vtrans_h<<<dim3(Tn/32, Hn/32, Bn*NKVn), dim3(32, 8)>>>(qkv, vT);

    // 3) causal GQA flash attention (HMMA fp16), writes ctx fp16
    attn_mma<<<dim3(Tn / 128, NQn, Bn), 256, A_SMEM_B>>>(qh, kh, vT, ctxh);

    // 4) output projection
    hgemm_pipe<<<dim3(Cn/128, BTn/128), 256, G_SMEM_B>>>(ctxh, woh, out, BTn, Cn, NQn*Hn);
}

// round 10
// speedup vs baseline: 5.1607x; 1.0099x over previous
#include <cuda_runtime.h>
#include <cuda_fp16.h>
#include <cstdint>

// Problem constants
#define Bn   2
#define Tn   2048
#define Cn   2048
#define NQn  16
#define NKVn 4
#define Hn   128
#define BTn  (Bn*Tn)        // 4096
#define NQKV 3072           // 2048 q + 512 k + 512 v
#define SCALE 0.08838834764831845f  // 1/sqrt(128)

// ---------------- scratch (device globals) ------------------------------------
__device__ __half g_qkvh[BTn * NQKV];            // fused qkv proj fp16 [bt][3072]
__device__ __half g_xh[BTn * Cn];                // x fp16 [M][K]
__device__ __half g_wqkvh[NQKV * Cn];            // [Wq^T; Wk^T; Wv^T] fp16
__device__ __half g_woh[Cn * (NQn*Hn)];          // Wo^T fp16
__device__ __half g_ctxh[BTn * NQn * Hn];        // attention out fp16
__device__ __half g_qh[Bn * NQn * Tn * Hn];      // q fp16 [b][h][t][d]
__device__ __half g_kh[Bn * NKVn * Tn * Hn];     // k fp16 [b][kvh][t][d]

// ---------------- helpers ------------------------------------------------------
__device__ __forceinline__ uint32_t smem_u32(const void* p) {
    uint32_t a;
    asm("{ .reg .u64 t; cvta.to.shared.u64 t, %1; cvt.u32.u64 %0, t; }" : "=r"(a) : "l"(p));
    return a;
}
__device__ __forceinline__ void ldmatrix_x4(uint32_t& r0, uint32_t& r1,
                                            uint32_t& r2, uint32_t& r3, uint32_t addr) {
    asm volatile("ldmatrix.sync.aligned.m8n8.x4.shared.b16 {%0,%1,%2,%3}, [%4];"
                 : "=r"(r0), "=r"(r1), "=r"(r2), "=r"(r3) : "r"(addr));
}
__device__ __forceinline__ void ldmatrix_x4_trans(uint32_t& r0, uint32_t& r1,
                                                  uint32_t& r2, uint32_t& r3, uint32_t addr) {
    asm volatile("ldmatrix.sync.aligned.m8n8.x4.trans.shared.b16 {%0,%1,%2,%3}, [%4];"
                 : "=r"(r0), "=r"(r1), "=r"(r2), "=r"(r3) : "r"(addr));
}
__device__ __forceinline__ void mma16816(float* d, const uint32_t* a, const uint32_t* b) {
    asm volatile(
        "mma.sync.aligned.m16n8k16.row.col.f32.f16.f16.f32 "
        "{%0,%1,%2,%3}, {%4,%5,%6,%7}, {%8,%9}, {%0,%1,%2,%3};"
        : "+f"(d[0]), "+f"(d[1]), "+f"(d[2]), "+f"(d[3])
        : "r"(a[0]), "r"(a[1]), "r"(a[2]), "r"(a[3]), "r"(b[0]), "r"(b[1]));
}
__device__ __forceinline__ void cp16(uint32_t dst, const void* src) {
    asm volatile("cp.async.cg.shared.global [%0], [%1], 16;"
                 :: "r"(dst), "l"(__cvta_generic_to_global(src)));
}
#define CP_COMMIT() asm volatile("cp.async.commit_group;")

// ---------------- fp32 -> fp16 elementwise ------------------------------------
__global__ void f32_to_f16_kernel(const float* __restrict__ in, __half* __restrict__ out, int n4) {
    int i = blockIdx.x * blockDim.x + threadIdx.x;
    if (i < n4) {
        float4 v = ((const float4*)in)[i];
        ((__half2*)out)[2*i]   = __floats2half2_rn(v.x, v.y);
        ((__half2*)out)[2*i+1] = __floats2half2_rn(v.z, v.w);
    }
}

// ---------------- W [K][N] f32 -> Wt [N][K] f16 (tiled transpose) --------------
__global__ void transpose_to_f16_kernel(const float* __restrict__ W, __half* __restrict__ Wt,
                                        int K, int N) {
    __shared__ float tile[32][33];
    int n0 = blockIdx.x * 32, k0 = blockIdx.y * 32;
    int tx = threadIdx.x, ty = threadIdx.y;   // 32 x 8
    #pragma unroll
    for (int i = 0; i < 32; i += 8)
        tile[ty + i][tx] = W[(size_t)(k0 + ty + i) * N + n0 + tx];
    __syncthreads();
    #pragma unroll
    for (int i = 0; i < 32; i += 8)
        Wt[(size_t)(n0 + ty + i) * K + k0 + tx] = __float2half(tile[tx][ty + i]);
}

// ---------------- HMMA GEMM 128x256, 3-stage cp.async pipeline -----------------
// C[M,N] = A[M,K]f16 @ Bt[N,K]f16^T ; warp tile 64x64 (2x4 warps), K-chunk 32.
#define GP 40
#define G_AH (128*GP)                     // A tile halfs (5120)
#define G_BH (256*GP)                     // B tile halfs (10240)
#define G_STAGE_H (G_AH + G_BH)           // 15360 halfs / stage
#define GSTG 3
#define G_SMEM_B (GSTG * G_STAGE_H * 2)   // 92160 bytes
template<typename OutT>
__global__ void __launch_bounds__(256) hgemm_pipe(const __half* __restrict__ A,
                                                  const __half* __restrict__ B,
                                                  OutT* __restrict__ C,
                                                  int M, int N, int K) {
    extern __shared__ __half hsm[];
    uint32_t smb = smem_u32(hsm);
    int tid = threadIdx.x;
    int lane = tid & 31, wid = tid >> 5;
    int wm = wid >> 2, wn = wid & 3;          // 2 x 4 warp grid, warp tile 64x64
    int m0 = blockIdx.y << 7, n0 = blockIdx.x << 8;

    // cp.async mapping: A 512 chunks (2/thread), B 1024 chunks (4/thread)
    int ar = tid >> 1, ac = (tid & 1) << 1;   // A: f = tid+i*256 -> r=f>>2... use loop
    (void)ar; (void)ac;
    const int NC = K >> 5;

    auto issue = [&](int c) {
        int s = c % GSTG;
        uint32_t base = smb + s * (G_STAGE_H * 2);
        #pragma unroll
        for (int i = 0; i < 2; i++) {
            int f = tid + i * 256; int r = f >> 2, cc = (f & 3) * 8;
            cp16(base + (r * GP + cc) * 2, A + (size_t)(m0 + r) * K + c * 32 + cc);
        }
        #pragma unroll
        for (int i = 0; i < 4; i++) {
            int f = tid + i * 256; int r = f >> 2, cc = (f & 3) * 8;
            cp16(base + (G_AH + r * GP + cc) * 2, B + (size_t)(n0 + r) * K + c * 32 + cc);
        }
        CP_COMMIT();
    };

    issue(0); issue(1);

    float acc[4][8][4];
    #pragma unroll
    for (int i = 0; i < 4; i++)
        #pragma unroll
        for (int j = 0; j < 8; j++)
            #pragma unroll
            for (int k = 0; k < 4; k++) acc[i][j][k] = 0.f;

    int lrow = lane & 15, lhalf = lane >> 4;

    for (int c = 0; c < NC; c++) {
        asm volatile("cp.async.wait_group 1;");
        __syncthreads();
        if (c + 2 < NC) issue(c + 2);

        uint32_t sbase = smb + (c % GSTG) * (G_STAGE_H * 2);
        #pragma unroll
        for (int ks = 0; ks < 2; ks++) {
            uint32_t af[4][4];
            uint32_t bf[8][2];
            #pragma unroll
            for (int mt = 0; mt < 4; mt++) {
                uint32_t ad = sbase + ((wm*64 + mt*16 + lrow) * GP + ks*16 + lhalf*8) * 2;
                ldmatrix_x4(af[mt][0], af[mt][1], af[mt][2], af[mt][3], ad);
            }
            #pragma unroll
            for (int np = 0; np < 4; np++) {
                uint32_t bd = sbase + (G_AH + (wn*64 + np*16 + lrow) * GP + ks*16 + lhalf*8) * 2;
                uint32_t q0, q1, q2, q3;
                ldmatrix_x4(q0, q1, q2, q3, bd);
                bf[np*2+0][0] = q0; bf[np*2+1][0] = q1;
                bf[np*2+0][1] = q2; bf[np*2+1][1] = q3;
            }
            #pragma unroll
            for (int mt = 0; mt < 4; mt++)
                #pragma unroll
                for (int nt = 0; nt < 8; nt++)
                    mma16816(acc[mt][nt], af[mt], bf[nt]);
        }
    }

    int er = lane >> 2, ec = (lane & 3) * 2;
    #pragma unroll
    for (int mt = 0; mt < 4; mt++) {
        int row = m0 + wm*64 + mt*16 + er;
        OutT* Cr0 = C + (size_t)row * N + n0 + wn*64;
        OutT* Cr1 = Cr0 + 8 * N;
        #pragma unroll
        for (int nt = 0; nt < 8; nt++) {
            if constexpr (sizeof(OutT) == 2) {
                *(__half2*)&Cr0[nt*8 + ec] = __floats2half2_rn(acc[mt][nt][0], acc[mt][nt][1]);
                *(__half2*)&Cr1[nt*8 + ec] = __floats2half2_rn(acc[mt][nt][2], acc[mt][nt][3]);
            } else {
                *(float2*)&Cr0[nt*8 + ec] = make_float2(acc[mt][nt][0], acc[mt][nt][1]);
                *(float2*)&Cr1[nt*8 + ec] = make_float2(acc[mt][nt][2], acc[mt][nt][3]);
            }
        }
    }
}

// ---------------- RMSNorm + RoPE (fp16 in) -> fp16 [b][h][t][d] ----------------
__global__ void normrope_h(const __half* __restrict__ proj, int stride, int coloff,
                           const float* __restrict__ w,
                           const float* __restrict__ cosb,
                           const float* __restrict__ sinb,
                           __half* __restrict__ outh, int NH) {
    int gw = (blockIdx.x * blockDim.x + threadIdx.x) >> 5;
    int lane = threadIdx.x & 31;
    if (gw >= Bn * Tn * NH) return;
    int h = gw % NH;
    int bt = gw / NH;
    int t = bt % Tn;
    int b = bt / Tn;

    const __half* p = proj + (size_t)bt * stride + coloff + h * Hn;
    int d0 = lane * 2;
    float2 xa = __half22float2(*(const __half2*)(p + d0));
    float2 xb = __half22float2(*(const __half2*)(p + d0 + 64));
    float ss = xa.x*xa.x + xa.y*xa.y + xb.x*xb.x + xb.y*xb.y;
    #pragma unroll
    for (int o = 16; o; o >>= 1) ss += __shfl_xor_sync(0xffffffffu, ss, o);
    float inv = rsqrtf(ss * (1.0f / 128.0f) + 1e-6f);
    float2 wa = *(const float2*)(w + d0);
    float2 wb = *(const float2*)(w + d0 + 64);
    xa.x *= inv * wa.x; xa.y *= inv * wa.y;
    xb.x *= inv * wb.x; xb.y *= inv * wb.y;
    const float* cp = cosb + (size_t)t * Hn;
    const float* sp = sinb + (size_t)t * Hn;
    float2 ca = *(const float2*)(cp + d0), cb = *(const float2*)(cp + d0 + 64);
    float2 sa = *(const float2*)(sp + d0), sb = *(const float2*)(sp + d0 + 64);
    float ya0 = xa.x * ca.x - xb.x * sa.x;
    float ya1 = xa.y * ca.y - xb.y * sa.y;
    float yb0 = xb.x * cb.x + xa.x * sb.x;
    float yb1 = xb.y * cb.y + xa.y * sb.y;
    __half* o = outh + ((size_t)(b * NH + h) * Tn + t) * Hn;
    *(__half2*)(o + d0)      = __floats2half2_rn(ya0, ya1);
    *(__half2*)(o + d0 + 64) = __floats2half2_rn(yb0, yb1);
}

// ---------------- HMMA flash attention (causal, GQA), cp.async 2-stage ---------
// K tile [64 t][128 d] pitch 136; V tile [64 t][128 d] pitch 136 (trans ldmatrix).
#define AKP 136
#define A_KB (64 * AKP)               // halfs per K tile (8704)
#define A_STAGE_H (2 * A_KB)          // stage halfs (17408)
#define A_SMEM_B (2 * A_STAGE_H * 2)  // 69632 bytes
__global__ void __launch_bounds__(256) attn_mma(const __half* __restrict__ qh,
                                                const __half* __restrict__ kh,
                                                const __half* __restrict__ qkvh,
                                                __half* __restrict__ ctxh) {
    extern __shared__ __half asm_[];
    uint32_t smb = smem_u32(asm_);

    int tid = threadIdx.x, lane = tid & 31, w = tid >> 5;
    int q0 = blockIdx.x << 7;
    int h = blockIdx.y, b = blockIdx.z;
    int kvh = h >> 2;

    const __half* qb = qh + ((size_t)(b * NQn + h) * Tn + q0) * Hn;
    const __half* kb = kh + (size_t)(b * NKVn + kvh) * Tn * Hn;
    const __half* vb = qkvh + (size_t)b * Tn * NQKV + 2560 + kvh * Hn;  // row t: + t*NQKV

    // stage Q [128][128] into smem (pitch AKP), extract fragments
    #pragma unroll
    for (int i = 0; i < 8; i++) {
        int f = tid + i * 256; int r = f >> 4, c8 = (f & 15) << 3;
        *(uint4*)&asm_[r * AKP + c8] = *(const uint4*)(qb + (size_t)r * Hn + c8);
    }
    __syncthreads();
    int lrow = lane & 15, lhalf = lane >> 4;
    uint32_t qf[8][4];
    #pragma unroll
    for (int ks = 0; ks < 8; ks++) {
        uint32_t ad = smb + ((w * 16 + lrow) * AKP + ks * 16 + lhalf * 8) * 2;
        ldmatrix_x4(qf[ks][0], qf[ks][1], qf[ks][2], qf[ks][3], ad);
    }
    __syncthreads();

    auto issue_kv = [&](int jt) {
        uint32_t base = smb + (jt & 1) * (A_STAGE_H * 2);
        int j0 = jt << 6;
        #pragma unroll
        for (int i = 0; i < 4; i++) {
            int f = tid + i * 256; int r = f >> 4, c8 = (f & 15) << 3;
            cp16(base + (r * AKP + c8) * 2, kb + (size_t)(j0 + r) * Hn + c8);
        }
        #pragma unroll
        for (int i = 0; i < 4; i++) {
            int f = tid + i * 256; int r = f >> 4, c8 = (f & 15) << 3;
            cp16(base + (A_KB + r * AKP + c8) * 2, vb + (size_t)(j0 + r) * NQKV + c8);
        }
        CP_COMMIT();
    };

    const int NT = (q0 >> 6) + 2;
    issue_kv(0);

    float oacc[16][4];
    #pragma unroll
    for (int i = 0; i < 16; i++) { oacc[i][0]=0.f; oacc[i][1]=0.f; oacc[i][2]=0.f; oacc[i][3]=0.f; }
    float m0 = -1e30f, m1 = -1e30f, l0 = 0.f, l1 = 0.f;
    int ec = (lane & 3) * 2;
    int r0 = q0 + w * 16 + (lane >> 2);
    int r1 = r0 + 8;

    for (int jt = 0; jt < NT; jt++) {
        int j0 = jt << 6;
        if (jt + 1 < NT) {
            issue_kv(jt + 1);
            asm volatile("cp.async.wait_group 1;");
        } else {
            asm volatile("cp.async.wait_group 0;");
        }
        __syncthreads();
        uint32_t sbase = smb + (jt & 1) * (A_STAGE_H * 2);

        // S = Q @ K^T
        float sacc[8][4];
        #pragma unroll
        for (int i = 0; i < 8; i++) { sacc[i][0]=0.f; sacc[i][1]=0.f; sacc[i][2]=0.f; sacc[i][3]=0.f; }
        #pragma unroll
        for (int ks = 0; ks < 8; ks++) {
            #pragma unroll
            for (int np = 0; np < 4; np++) {
                uint32_t ad = sbase + ((np * 16 + lrow) * AKP + ks * 16 + lhalf * 8) * 2;
                uint32_t t0, t1, t2, t3;
                ldmatrix_x4(t0, t1, t2, t3, ad);
                uint32_t b0[2] = {t0, t2}, b1[2] = {t1, t3};
                mma16816(sacc[np * 2],     qf[ks], b0);
                mma16816(sacc[np * 2 + 1], qf[ks], b1);
            }
        }

        // scale + causal mask
        #pragma unroll
        for (int nt = 0; nt < 8; nt++) {
            int c = j0 + nt * 8 + ec;
            sacc[nt][0] = (c     > r0) ? -1e30f : sacc[nt][0] * SCALE;
            sacc[nt][1] = (c + 1 > r0) ? -1e30f : sacc[nt][1] * SCALE;
            sacc[nt][2] = (c     > r1) ? -1e30f : sacc[nt][2] * SCALE;
            sacc[nt][3] = (c + 1 > r1) ? -1e30f : sacc[nt][3] * SCALE;
        }

        // online softmax
        float tm0 = -1e30f, tm1 = -1e30f;
        #pragma unroll
        for (int nt = 0; nt < 8; nt++) {
            tm0 = fmaxf(tm0, fmaxf(sacc[nt][0], sacc[nt][1]));
            tm1 = fmaxf(tm1, fmaxf(sacc[nt][2], sacc[nt][3]));
        }
        tm0 = fmaxf(tm0, __shfl_xor_sync(0xffffffffu, tm0, 1));
        tm0 = fmaxf(tm0, __shfl_xor_sync(0xffffffffu, tm0, 2));
        tm1 = fmaxf(tm1, __shfl_xor_sync(0xffffffffu, tm1, 1));
        tm1 = fmaxf(tm1, __shfl_xor_sync(0xffffffffu, tm1, 2));
        float mn0 = fmaxf(m0, tm0), mn1 = fmaxf(m1, tm1);
        float al0 = __expf(m0 - mn0), al1 = __expf(m1 - mn1);
        m0 = mn0; m1 = mn1;

        float rs0 = 0.f, rs1 = 0.f;
        uint32_t pf[4][4];
        #pragma unroll
        for (int nt = 0; nt < 8; nt++) {
            float p0 = __expf(sacc[nt][0] - mn0);
            float p1 = __expf(sacc[nt][1] - mn0);
            float p2 = __expf(sacc[nt][2] - mn1);
            float p3 = __expf(sacc[nt][3] - mn1);
            rs0 += p0 + p1; rs1 += p2 + p3;
            __half2 v01 = __floats2half2_rn(p0, p1);
            __half2 v23 = __floats2half2_rn(p2, p3);
            int kt = nt >> 1;
            if ((nt & 1) == 0) {
                pf[kt][0] = *(uint32_t*)&v01;
                pf[kt][1] = *(uint32_t*)&v23;
            } else {
                pf[kt][2] = *(uint32_t*)&v01;
                pf[kt][3] = *(uint32_t*)&v23;
            }
        }
        rs0 += __shfl_xor_sync(0xffffffffu, rs0, 1);
        rs0 += __shfl_xor_sync(0xffffffffu, rs0, 2);
        rs1 += __shfl_xor_sync(0xffffffffu, rs1, 1);
        rs1 += __shfl_xor_sync(0xffffffffu, rs1, 2);
        l0 = l0 * al0 + rs0;
        l1 = l1 * al1 + rs1;

        #pragma unroll
        for (int dt = 0; dt < 16; dt++) {
            oacc[dt][0] *= al0; oacc[dt][1] *= al0;
            oacc[dt][2] *= al1; oacc[dt][3] *= al1;
        }

        // O += P @ V : V smem rows = t (k dim), cols = d (n dim); trans ldmatrix
        #pragma unroll
        for (int kt = 0; kt < 4; kt++) {
            #pragma unroll
            for (int np = 0; np < 8; np++) {
                uint32_t ad = sbase + (A_KB + (kt * 16 + lrow) * AKP + np * 16 + lhalf * 8) * 2;
                uint32_t t0, t1, t2, t3;
                ldmatrix_x4_trans(t0, t1, t2, t3, ad);
                uint32_t b0[2] = {t0, t1}, b1[2] = {t2, t3};
                mma16816(oacc[np * 2],     pf[kt], b0);
                mma16816(oacc[np * 2 + 1], pf[kt], b1);
            }
        }
        __syncthreads();
    }

    // epilogue
    float inv0 = 1.0f / l0, inv1 = 1.0f / l1;
    __half* o0 = ctxh + (size_t)(b * Tn + r0) * (NQn * Hn) + h * Hn;
    __half* o1 = ctxh + (size_t)(b * Tn + r1) * (NQn * Hn) + h * Hn;
    #pragma unroll
    for (int dt = 0; dt < 16; dt++) {
        __half2 w0 = __floats2half2_rn(oacc[dt][0] * inv0, oacc[dt][1] * inv0);
        __half2 w1 = __floats2half2_rn(oacc[dt][2] * inv1, oacc[dt][3] * inv1);
        *(__half2*)&o0[dt * 8 + ec] = w0;
        *(__half2*)&o1[dt * 8 + ec] = w1;
    }
}

// ---------------- launch ------------------------------------------------------
extern "C" void kernel_launch(void* const* d_in, const int* in_sizes, int n_in,
                              void* d_out, int out_size) {
    (void)in_sizes; (void)n_in; (void)out_size;
    const float* x   = (const float*)d_in[0];
    const float* Wq  = (const float*)d_in[1];
    const float* Wk  = (const float*)d_in[2];
    const float* Wv  = (const float*)d_in[3];
    const float* Wo  = (const float*)d_in[4];
    const float* qnw = (const float*)d_in[5];
    const float* knw = (const float*)d_in[6];
    const float* cosb = (const float*)d_in[7];
    const float* sinb = (const float*)d_in[8];
    float* out = (float*)d_out;

    __half *qkvh, *xh, *wqkvh, *woh, *ctxh, *qh, *kh;
    cudaGetSymbolAddress((void**)&qkvh,  g_qkvh);
    cudaGetSymbolAddress((void**)&xh,    g_xh);
    cudaGetSymbolAddress((void**)&wqkvh, g_wqkvh);
    cudaGetSymbolAddress((void**)&woh,   g_woh);
    cudaGetSymbolAddress((void**)&ctxh,  g_ctxh);
    cudaGetSymbolAddress((void**)&qh,    g_qh);
    cudaGetSymbolAddress((void**)&kh,    g_kh);

    cudaFuncSetAttribute(hgemm_pipe<__half>, cudaFuncAttributeMaxDynamicSharedMemorySize, G_SMEM_B);
    cudaFuncSetAttribute(hgemm_pipe<float>,  cudaFuncAttributeMaxDynamicSharedMemorySize, G_SMEM_B);
    cudaFuncSetAttribute(attn_mma, cudaFuncAttributeMaxDynamicSharedMemorySize, A_SMEM_B);

    // 0) weight transposes + x conversion
    transpose_to_f16_kernel<<<dim3((NQn*Hn)/32, Cn/32), dim3(32, 8)>>>(Wq, wqkvh, Cn, NQn*Hn);
    transpose_to_f16_kernel<<<dim3((NKVn*Hn)/32, Cn/32), dim3(32, 8)>>>(Wk, wqkvh + (size_t)2048*Cn, Cn, NKVn*Hn);
    transpose_to_f16_kernel<<<dim3((NKVn*Hn)/32, Cn/32), dim3(32, 8)>>>(Wv, wqkvh + (size_t)2560*Cn, Cn, NKVn*Hn);
    transpose_to_f16_kernel<<<dim3(Cn/32, (NQn*Hn)/32), dim3(32, 8)>>>(Wo, woh, NQn*Hn, Cn);
    f32_to_f16_kernel<<<(BTn * Cn / 4 + 255) / 256, 256>>>(x, xh, BTn * Cn / 4);

    // 1) fused QKV projection -> fp16
    hgemm_pipe<__half><<<dim3(NQKV/256, BTn/128), 256, G_SMEM_B>>>(xh, wqkvh, qkvh, BTn, NQKV, Cn);

    // 2) rmsnorm + rope -> fp16 [b][h][t][d]
    normrope_h<<<(Bn * Tn * NQn) / 8, 256>>>(qkvh, NQKV, 0,    qnw, cosb, sinb, qh, NQn);
    normrope_h<<<(Bn * Tn * NKVn) / 8, 256>>>(qkvh, NQKV, 2048, knw, cosb, sinb, kh, NKVn);

    // 3) causal GQA flash attention (V read in-place from qkvh)
    attn_mma<<<dim3(Tn / 128, NQn, Bn), 256, A_SMEM_B>>>(qh, kh, qkvh, ctxh);

    // 4) output projection -> f32
    hgemm_pipe<float><<<dim3(Cn/256, BTn/128), 256, G_SMEM_B>>>(ctxh, woh, out, BTn, Cn, NQn*Hn);
}

// round 11
// speedup vs baseline: 5.6907x; 1.1027x over previous
#include <cuda_runtime.h>
#include <cuda_fp16.h>
#include <cstdint>

// Problem constants
#define Bn   2
#define Tn   2048
#define Cn   2048
#define NQn  16
#define NKVn 4
#define Hn   128
#define BTn  (Bn*Tn)        // 4096
#define NQKV 3072           // 2048 q + 512 k + 512 v
#define SCALE 0.08838834764831845f  // 1/sqrt(128)

// ---------------- scratch (device globals) ------------------------------------
__device__ __half g_qkvh[BTn * NQKV];            // fused qkv proj fp16 [bt][3072]
__device__ __half g_xh[BTn * Cn];                // x fp16 [M][K]
__device__ __half g_wqkvh[Cn * NQKV];            // [Wq | Wk | Wv] fp16 [K=2048][3072]
__device__ __half g_woh[(NQn*Hn) * Cn];          // Wo fp16 [K=2048][N=2048]
__device__ __half g_ctxh[BTn * NQn * Hn];        // attention out fp16
__device__ __half g_qh[Bn * NQn * Tn * Hn];      // q fp16 [b][h][t][d]
__device__ __half g_kh[Bn * NKVn * Tn * Hn];     // k fp16 [b][kvh][t][d]

// ---------------- helpers ------------------------------------------------------
__device__ __forceinline__ uint32_t smem_u32(const void* p) {
    uint32_t a;
    asm("{ .reg .u64 t; cvta.to.shared.u64 t, %1; cvt.u32.u64 %0, t; }" : "=r"(a) : "l"(p));
    return a;
}
__device__ __forceinline__ void ldmatrix_x4(uint32_t& r0, uint32_t& r1,
                                            uint32_t& r2, uint32_t& r3, uint32_t addr) {
    asm volatile("ldmatrix.sync.aligned.m8n8.x4.shared.b16 {%0,%1,%2,%3}, [%4];"
                 : "=r"(r0), "=r"(r1), "=r"(r2), "=r"(r3) : "r"(addr));
}
__device__ __forceinline__ void ldmatrix_x4_trans(uint32_t& r0, uint32_t& r1,
                                                  uint32_t& r2, uint32_t& r3, uint32_t addr) {
    asm volatile("ldmatrix.sync.aligned.m8n8.x4.trans.shared.b16 {%0,%1,%2,%3}, [%4];"
                 : "=r"(r0), "=r"(r1), "=r"(r2), "=r"(r3) : "r"(addr));
}
__device__ __forceinline__ void mma16816(float* d, const uint32_t* a, const uint32_t* b) {
    asm volatile(
        "mma.sync.aligned.m16n8k16.row.col.f32.f16.f16.f32 "
        "{%0,%1,%2,%3}, {%4,%5,%6,%7}, {%8,%9}, {%0,%1,%2,%3};"
        : "+f"(d[0]), "+f"(d[1]), "+f"(d[2]), "+f"(d[3])
        : "r"(a[0]), "r"(a[1]), "r"(a[2]), "r"(a[3]), "r"(b[0]), "r"(b[1]));
}
__device__ __forceinline__ void cp16(uint32_t dst, const void* src) {
    asm volatile("cp.async.cg.shared.global [%0], [%1], 16;"
                 :: "r"(dst), "l"(__cvta_generic_to_global(src)));
}
#define CP_COMMIT() asm volatile("cp.async.commit_group;")

// ---------------- fp32 -> fp16 elementwise ------------------------------------
__global__ void f32_to_f16_kernel(const float* __restrict__ in, __half* __restrict__ out, int n4) {
    int i = blockIdx.x * blockDim.x + threadIdx.x;
    if (i < n4) {
        float4 v = ((const float4*)in)[i];
        ((__half2*)out)[2*i]   = __floats2half2_rn(v.x, v.y);
        ((__half2*)out)[2*i+1] = __floats2half2_rn(v.z, v.w);
    }
}

// ---------------- W [K][N] f32 -> fp16 into combined [K][outStride] ------------
__global__ void wconv_kernel(const float* __restrict__ W, __half* __restrict__ out,
                             int N, int outStride, int outOff, int total2) {
    int i = blockIdx.x * blockDim.x + threadIdx.x;   // over K*N/2
    if (i < total2) {
        float2 v = ((const float2*)W)[i];
        int row = i / (N >> 1), c2 = i % (N >> 1);
        *(__half2*)&out[(size_t)row * outStride + outOff + 2 * c2] =
            __floats2half2_rn(v.x, v.y);
    }
}

// ---------------- HMMA GEMM 128x256, 3-stage cp.async, B natural [K][N] -------
// C[M,N] = A[M,K]f16 @ B[K,N]f16 ; warp tile 64x64 (2x4 warps), K-chunk 32.
// B fragments via trans ldmatrix (same mapping as attention P·V, validated R10).
#define GP 40
#define BP 264                            // B smem pitch (halfs) = 33 x 16B
#define G_AH (128*GP)                     // A tile halfs (5120)
#define G_BH (32*BP)                      // B tile halfs (8448)
#define G_STAGE_H (G_AH + G_BH)           // 13568 halfs / stage
#define GSTG 3
#define G_SMEM_B (GSTG * G_STAGE_H * 2)   // 81408 bytes
template<typename OutT>
__global__ void __launch_bounds__(256) hgemm_pipe(const __half* __restrict__ A,
                                                  const __half* __restrict__ B,
                                                  OutT* __restrict__ C,
                                                  int M, int N, int K, int ldB) {
    extern __shared__ __half hsm[];
    uint32_t smb = smem_u32(hsm);
    int tid = threadIdx.x;
    int lane = tid & 31, wid = tid >> 5;
    int wm = wid >> 2, wn = wid & 3;          // 2 x 4 warp grid, warp tile 64x64
    int m0 = blockIdx.y << 7, n0 = blockIdx.x << 8;

    const int NC = K >> 5;

    auto issue = [&](int c) {
        int s = c % GSTG;
        uint32_t base = smb + s * (G_STAGE_H * 2);
        #pragma unroll
        for (int i = 0; i < 2; i++) {
            int f = tid + i * 256; int r = f >> 2, cc = (f & 3) * 8;
            cp16(base + (r * GP + cc) * 2, A + (size_t)(m0 + r) * K + c * 32 + cc);
        }
        #pragma unroll
        for (int i = 0; i < 4; i++) {
            int f = tid + i * 256; int kr = f >> 5, nc = (f & 31) * 8;
            cp16(base + (G_AH + kr * BP + nc) * 2,
                 B + (size_t)(c * 32 + kr) * ldB + n0 + nc);
        }
        CP_COMMIT();
    };

    issue(0); issue(1);

    float acc[4][8][4];
    #pragma unroll
    for (int i = 0; i < 4; i++)
        #pragma unroll
        for (int j = 0; j < 8; j++)
            #pragma unroll
            for (int k = 0; k < 4; k++) acc[i][j][k] = 0.f;

    int lrow = lane & 15, lhalf = lane >> 4;

    for (int c = 0; c < NC; c++) {
        asm volatile("cp.async.wait_group 1;");
        __syncthreads();
        if (c + 2 < NC) issue(c + 2);

        uint32_t sbase = smb + (c % GSTG) * (G_STAGE_H * 2);
        #pragma unroll
        for (int ks = 0; ks < 2; ks++) {
            uint32_t af[4][4];
            uint32_t bf[8][2];
            #pragma unroll
            for (int mt = 0; mt < 4; mt++) {
                uint32_t ad = sbase + ((wm*64 + mt*16 + lrow) * GP + ks*16 + lhalf*8) * 2;
                ldmatrix_x4(af[mt][0], af[mt][1], af[mt][2], af[mt][3], ad);
            }
            #pragma unroll
            for (int np = 0; np < 4; np++) {
                uint32_t bd = sbase + (G_AH + (ks*16 + lrow) * BP + wn*64 + np*16 + lhalf*8) * 2;
                uint32_t q0, q1, q2, q3;
                ldmatrix_x4_trans(q0, q1, q2, q3, bd);
                bf[np*2+0][0] = q0; bf[np*2+0][1] = q1;
                bf[np*2+1][0] = q2; bf[np*2+1][1] = q3;
            }
            #pragma unroll
            for (int mt = 0; mt < 4; mt++)
                #pragma unroll
                for (int nt = 0; nt < 8; nt++)
                    mma16816(acc[mt][nt], af[mt], bf[nt]);
        }
    }

    int er = lane >> 2, ec = (lane & 3) * 2;
    #pragma unroll
    for (int mt = 0; mt < 4; mt++) {
        int row = m0 + wm*64 + mt*16 + er;
        OutT* Cr0 = C + (size_t)row * N + n0 + wn*64;
        OutT* Cr1 = Cr0 + 8 * N;
        #pragma unroll
        for (int nt = 0; nt < 8; nt++) {
            if constexpr (sizeof(OutT) == 2) {
                *(__half2*)&Cr0[nt*8 + ec] = __floats2half2_rn(acc[mt][nt][0], acc[mt][nt][1]);
                *(__half2*)&Cr1[nt*8 + ec] = __floats2half2_rn(acc[mt][nt][2], acc[mt][nt][3]);
            } else {
                *(float2*)&Cr0[nt*8 + ec] = make_float2(acc[mt][nt][0], acc[mt][nt][1]);
                *(float2*)&Cr1[nt*8 + ec] = make_float2(acc[mt][nt][2], acc[mt][nt][3]);
            }
        }
    }
}

// ---------------- RMSNorm + RoPE (fp16 in) -> fp16 [b][h][t][d] ----------------
__global__ void normrope_h(const __half* __restrict__ proj, int stride, int coloff,
                           const float* __restrict__ w,
                           const float* __restrict__ cosb,
                           const float* __restrict__ sinb,
                           __half* __restrict__ outh, int NH) {
    int gw = (blockIdx.x * blockDim.x + threadIdx.x) >> 5;
    int lane = threadIdx.x & 31;
    if (gw >= Bn * Tn * NH) return;
    int h = gw % NH;
    int bt = gw / NH;
    int t = bt % Tn;
    int b = bt / Tn;

    const __half* p = proj + (size_t)bt * stride + coloff + h * Hn;
    int d0 = lane * 2;
    float2 xa = __half22float2(*(const __half2*)(p + d0));
    float2 xb = __half22float2(*(const __half2*)(p + d0 + 64));
    float ss = xa.x*xa.x + xa.y*xa.y + xb.x*xb.x + xb.y*xb.y;
    #pragma unroll
    for (int o = 16; o; o >>= 1) ss += __shfl_xor_sync(0xffffffffu, ss, o);
    float inv = rsqrtf(ss * (1.0f / 128.0f) + 1e-6f);
    float2 wa = *(const float2*)(w + d0);
    float2 wb = *(const float2*)(w + d0 + 64);
    xa.x *= inv * wa.x; xa.y *= inv * wa.y;
    xb.x *= inv * wb.x; xb.y *= inv * wb.y;
    const float* cp = cosb + (size_t)t * Hn;
    const float* sp = sinb + (size_t)t * Hn;
    float2 ca = *(const float2*)(cp + d0), cb = *(const float2*)(cp + d0 + 64);
    float2 sa = *(const float2*)(sp + d0), sb = *(const float2*)(sp + d0 + 64);
    float ya0 = xa.x * ca.x - xb.x * sa.x;
    float ya1 = xa.y * ca.y - xb.y * sa.y;
    float yb0 = xb.x * cb.x + xa.x * sb.x;
    float yb1 = xb.y * cb.y + xa.y * sb.y;
    __half* o = outh + ((size_t)(b * NH + h) * Tn + t) * Hn;
    *(__half2*)(o + d0)      = __floats2half2_rn(ya0, ya1);
    *(__half2*)(o + d0 + 64) = __floats2half2_rn(yb0, yb1);
}

// ---------------- HMMA flash attention (causal, GQA) ---------------------------
// 64 q-rows per CTA, 128 threads (4 warps x 16 rows), kv tiles of 64,
// cp.async double buffer, descending-q0 launch order for load balance.
#define AKP 136
#define A_KB (64 * AKP)               // halfs per K (or V) tile (8704)
#define A_STAGE_H (2 * A_KB)          // stage halfs (17408)
#define A_SMEM_B (2 * A_STAGE_H * 2)  // 69632 bytes
__global__ void __launch_bounds__(128) attn_mma(const __half* __restrict__ qh,
                                                const __half* __restrict__ kh,
                                                const __half* __restrict__ qkvh,
                                                __half* __restrict__ ctxh) {
    extern __shared__ __half asm_[];
    uint32_t smb = smem_u32(asm_);

    int tid = threadIdx.x, lane = tid & 31, w = tid >> 5;
    int q0 = (gridDim.x - 1 - blockIdx.x) << 6;    // descending work order
    int h = blockIdx.y, b = blockIdx.z;
    int kvh = h >> 2;

    const __half* qb = qh + ((size_t)(b * NQn + h) * Tn + q0) * Hn;
    const __half* kb = kh + (size_t)(b * NKVn + kvh) * Tn * Hn;
    const __half* vb = qkvh + (size_t)b * Tn * NQKV + 2560 + kvh * Hn;

    // stage Q [64][128] into smem (pitch AKP), extract fragments
    #pragma unroll
    for (int i = 0; i < 8; i++) {
        int f = tid + i * 128; int r = f >> 4, c8 = (f & 15) << 3;
        *(uint4*)&asm_[r * AKP + c8] = *(const uint4*)(qb + (size_t)r * Hn + c8);
    }
    __syncthreads();
    int lrow = lane & 15, lhalf = lane >> 4;
    uint32_t qf[8][4];
    #pragma unroll
    for (int ks = 0; ks < 8; ks++) {
        uint32_t ad = smb + ((w * 16 + lrow) * AKP + ks * 16 + lhalf * 8) * 2;
        ldmatrix_x4(qf[ks][0], qf[ks][1], qf[ks][2], qf[ks][3], ad);
    }
    __syncthreads();

    auto issue_kv = [&](int jt) {
        uint32_t base = smb + (jt & 1) * (A_STAGE_H * 2);
        int j0 = jt << 6;
        #pragma unroll
        for (int i = 0; i < 8; i++) {
            int f = tid + i * 128; int r = f >> 4, c8 = (f & 15) << 3;
            cp16(base + (r * AKP + c8) * 2, kb + (size_t)(j0 + r) * Hn + c8);
        }
        #pragma unroll
        for (int i = 0; i < 8; i++) {
            int f = tid + i * 128; int r = f >> 4, c8 = (f & 15) << 3;
            cp16(base + (A_KB + r * AKP + c8) * 2, vb + (size_t)(j0 + r) * NQKV + c8);
        }
        CP_COMMIT();
    };

    const int NT = (q0 >> 6) + 1;
    issue_kv(0);

    float oacc[16][4];
    #pragma unroll
    for (int i = 0; i < 16; i++) { oacc[i][0]=0.f; oacc[i][1]=0.f; oacc[i][2]=0.f; oacc[i][3]=0.f; }
    float m0 = -1e30f, m1 = -1e30f, l0 = 0.f, l1 = 0.f;
    int ec = (lane & 3) * 2;
    int r0 = q0 + w * 16 + (lane >> 2);
    int r1 = r0 + 8;

    for (int jt = 0; jt < NT; jt++) {
        int j0 = jt << 6;
        if (jt + 1 < NT) {
            issue_kv(jt + 1);
            asm volatile("cp.async.wait_group 1;");
        } else {
            asm volatile("cp.async.wait_group 0;");
        }
        __syncthreads();
        uint32_t sbase = smb + (jt & 1) * (A_STAGE_H * 2);

        // S = Q @ K^T
        float sacc[8][4];
        #pragma unroll
        for (int i = 0; i < 8; i++) { sacc[i][0]=0.f; sacc[i][1]=0.f; sacc[i][2]=0.f; sacc[i][3]=0.f; }
        #pragma unroll
        for (int ks = 0; ks < 8; ks++) {
            #pragma unroll
            for (int np = 0; np < 4; np++) {
                uint32_t ad = sbase + ((np * 16 + lrow) * AKP + ks * 16 + lhalf * 8) * 2;
                uint32_t t0, t1, t2, t3;
                ldmatrix_x4(t0, t1, t2, t3, ad);
                uint32_t b0[2] = {t0, t2}, b1[2] = {t1, t3};
                mma16816(sacc[np * 2],     qf[ks], b0);
                mma16816(sacc[np * 2 + 1], qf[ks], b1);
            }
        }

        // scale + causal mask
        #pragma unroll
        for (int nt = 0; nt < 8; nt++) {
            int c = j0 + nt * 8 + ec;
            sacc[nt][0] = (c     > r0) ? -1e30f : sacc[nt][0] * SCALE;
            sacc[nt][1] = (c + 1 > r0) ? -1e30f : sacc[nt][1] * SCALE;
            sacc[nt][2] = (c     > r1) ? -1e30f : sacc[nt][2] * SCALE;
            sacc[nt][3] = (c + 1 > r1) ? -1e30f : sacc[nt][3] * SCALE;
        }

        // online softmax
        float tm0 = -1e30f, tm1 = -1e30f;
        #pragma unroll
        for (int nt = 0; nt < 8; nt++) {
            tm0 = fmaxf(tm0, fmaxf(sacc[nt][0], sacc[nt][1]));
            tm1 = fmaxf(tm1, fmaxf(sacc[nt][2], sacc[nt][3]));
        }
        tm0 = fmaxf(tm0, __shfl_xor_sync(0xffffffffu, tm0, 1));
        tm0 = fmaxf(tm0, __shfl_xor_sync(0xffffffffu, tm0, 2));
        tm1 = fmaxf(tm1, __shfl_xor_sync(0xffffffffu, tm1, 1));
        tm1 = fmaxf(tm1, __shfl_xor_sync(0xffffffffu, tm1, 2));
        float mn0 = fmaxf(m0, tm0), mn1 = fmaxf(m1, tm1);
        float al0 = __expf(m0 - mn0), al1 = __expf(m1 - mn1);
        m0 = mn0; m1 = mn1;

        float rs0 = 0.f, rs1 = 0.f;
        uint32_t pf[4][4];
        #pragma unroll
        for (int nt = 0; nt < 8; nt++) {
            float p0 = __expf(sacc[nt][0] - mn0);
            float p1 = __expf(sacc[nt][1] - mn0);
            float p2 = __expf(sacc[nt][2] - mn1);
            float p3 = __expf(sacc[nt][3] - mn1);
            rs0 += p0 + p1; rs1 += p2 + p3;
            __half2 v01 = __floats2half2_rn(p0, p1);
            __half2 v23 = __floats2half2_rn(p2, p3);
            int kt = nt >> 1;
            if ((nt & 1) == 0) {
                pf[kt][0] = *(uint32_t*)&v01;
                pf[kt][1] = *(uint32_t*)&v23;
            } else {
                pf[kt][2] = *(uint32_t*)&v01;
                pf[kt][3] = *(uint32_t*)&v23;
            }
        }
        rs0 += __shfl_xor_sync(0xffffffffu, rs0, 1);
        rs0 += __shfl_xor_sync(0xffffffffu, rs0, 2);
        rs1 += __shfl_xor_sync(0xffffffffu, rs1, 1);
        rs1 += __shfl_xor_sync(0xffffffffu, rs1, 2);
        l0 = l0 * al0 + rs0;
        l1 = l1 * al1 + rs1;

        #pragma unroll
        for (int dt = 0; dt < 16; dt++) {
            oacc[dt][0] *= al0; oacc[dt][1] *= al0;
            oacc[dt][2] *= al1; oacc[dt][3] *= al1;
        }

        // O += P @ V : V smem rows = t (k dim), cols = d (n dim); trans ldmatrix
        #pragma unroll
        for (int kt = 0; kt < 4; kt++) {
            #pragma unroll
            for (int np = 0; np < 8; np++) {
                uint32_t ad = sbase + (A_KB + (kt * 16 + lrow) * AKP + np * 16 + lhalf * 8) * 2;
                uint32_t t0, t1, t2, t3;
                ldmatrix_x4_trans(t0, t1, t2, t3, ad);
                uint32_t b0[2] = {t0, t1}, b1[2] = {t2, t3};
                mma16816(oacc[np * 2],     pf[kt], b0);
                mma16816(oacc[np * 2 + 1], pf[kt], b1);
            }
        }
        __syncthreads();
    }

    // epilogue
    float inv0 = 1.0f / l0, inv1 = 1.0f / l1;
    __half* o0 = ctxh + (size_t)(b * Tn + r0) * (NQn * Hn) + h * Hn;
    __half* o1 = ctxh + (size_t)(b * Tn + r1) * (NQn * Hn) + h * Hn;
    #pragma unroll
    for (int dt = 0; dt < 16; dt++) {
        __half2 w0 = __floats2half2_rn(oacc[dt][0] * inv0, oacc[dt][1] * inv0);
        __half2 w1 = __floats2half2_rn(oacc[dt][2] * inv1, oacc[dt][3] * inv1);
        *(__half2*)&o0[dt * 8 + ec] = w0;
        *(__half2*)&o1[dt * 8 + ec] = w1;
    }
}

// ---------------- launch ------------------------------------------------------
extern "C" void kernel_launch(void* const* d_in, const int* in_sizes, int n_in,
                              void* d_out, int out_size) {
    (void)in_sizes; (void)n_in; (void)out_size;
    const float* x   = (const float*)d_in[0];
    const float* Wq  = (const float*)d_in[1];
    const float* Wk  = (const float*)d_in[2];
    const float* Wv  = (const float*)d_in[3];
    const float* Wo  = (const float*)d_in[4];
    const float* qnw = (const float*)d_in[5];
    const float* knw = (const float*)d_in[6];
    const float* cosb = (const float*)d_in[7];
    const float* sinb = (const float*)d_in[8];
    float* out = (float*)d_out;

    __half *qkvh, *xh, *wqkvh, *woh, *ctxh, *qh, *kh;
    cudaGetSymbolAddress((void**)&qkvh,  g_qkvh);
    cudaGetSymbolAddress((void**)&xh,    g_xh);
    cudaGetSymbolAddress((void**)&wqkvh, g_wqkvh);
    cudaGetSymbolAddress((void**)&woh,   g_woh);
    cudaGetSymbolAddress((void**)&ctxh,  g_ctxh);
    cudaGetSymbolAddress((void**)&qh,    g_qh);
    cudaGetSymbolAddress((void**)&kh,    g_kh);

    cudaFuncSetAttribute(hgemm_pipe<__half>, cudaFuncAttributeMaxDynamicSharedMemorySize, G_SMEM_B);
    cudaFuncSetAttribute(hgemm_pipe<float>,  cudaFuncAttributeMaxDynamicSharedMemorySize, G_SMEM_B);
    cudaFuncSetAttribute(attn_mma, cudaFuncAttributeMaxDynamicSharedMemorySize, A_SMEM_B);

    // 0) conversions: weights fp16 (natural layout, no transpose), x fp16
    wconv_kernel<<<(Cn*2048/2 + 255)/256, 256>>>(Wq, wqkvh, 2048, NQKV, 0,    Cn*2048/2);
    wconv_kernel<<<(Cn*512/2  + 255)/256, 256>>>(Wk, wqkvh, 512,  NQKV, 2048, Cn*512/2);
    wconv_kernel<<<(Cn*512/2  + 255)/256, 256>>>(Wv, wqkvh, 512,  NQKV, 2560, Cn*512/2);
    wconv_kernel<<<(2048*Cn/2 + 255)/256, 256>>>(Wo, woh,   Cn,   Cn,   0,    2048*Cn/2);
    f32_to_f16_kernel<<<(BTn * Cn / 4 + 255) / 256, 256>>>(x, xh, BTn * Cn / 4);

    // 1) fused QKV projection -> fp16
    hgemm_pipe<__half><<<dim3(NQKV/256, BTn/128), 256, G_SMEM_B>>>(xh, wqkvh, qkvh, BTn, NQKV, Cn, NQKV);

    // 2) rmsnorm + rope -> fp16 [b][h][t][d]
    normrope_h<<<(Bn * Tn * NQn) / 8, 256>>>(qkvh, NQKV, 0,    qnw, cosb, sinb, qh, NQn);
    normrope_h<<<(Bn * Tn * NKVn) / 8, 256>>>(qkvh, NQKV, 2048, knw, cosb, sinb, kh, NKVn);

    // 3) causal GQA flash attention (V read in-place from qkvh)
    attn_mma<<<dim3(Tn / 64, NQn, Bn), 128, A_SMEM_B>>>(qh, kh, qkvh, ctxh);

    // 4) output projection -> f32
    hgemm_pipe<float><<<dim3(Cn/256, BTn/128), 256, G_SMEM_B>>>(ctxh, woh, out, BTn, Cn, NQn*Hn, Cn);
}